// round 1
// baseline (speedup 1.0000x reference)
#include <cuda_runtime.h>
#include <math.h>

// ---------------- problem constants ----------------
#define BB   16
#define SS   512
#define DD   512
#define LL   4
#define HH   8
#define QKD  256      // D/2
#define VV   512
#define FF   1408
#define RR   (BB*SS)      // 8192 rows
#define DQK  32
#define DV   64
#define EPS_RMS 1e-6f
#define EPS_BN  1e-5f
#define CAPV 15.0f

// ---------------- device scratch ----------------
__device__ float g_xn [RR*DD];
__device__ float g_h  [RR*DD];
__device__ float g_y  [RR*DD];
__device__ float g_q  [RR*QKD];
__device__ float g_k  [RR*QKD];
__device__ float g_v  [RR*VV];
__device__ float g_og [RR*VV];
__device__ float g_ht [RR*VV];
__device__ float g_ig [BB*HH*SS];
__device__ float g_fg [BB*HH*SS];
__device__ float g_bc [BB*HH*SS];
__device__ float g_mv [BB*HH*SS];
__device__ float g_gu1[RR*FF];
__device__ float g_gu2[RR*FF];
__device__ float g_part[64*1024];
__device__ float g_stats[1024];
__device__ float g_last[BB*DD];
__device__ float g_o1 [BB*256];
__device__ float g_o2 [BB];

__device__ __forceinline__ float softcapf(float x){ return CAPV * tanhf(x * (1.0f/CAPV)); }
__device__ __forceinline__ float logsigf(float x){ return fminf(x,0.f) - log1pf(expf(-fabsf(x))); }

// ---------------- input batch norm (over B*S per channel) ----------------
__global__ void bn_partial_kernel(const float* __restrict__ x){
    int c0 = threadIdx.x, c1 = threadIdx.x + 256;
    float s0=0,s1=0,q0=0,q1=0;
    const float* base = x + (size_t)blockIdx.x * 128 * DD;
    for (int r=0;r<128;r++){
        float v0 = base[(size_t)r*DD + c0];
        float v1 = base[(size_t)r*DD + c1];
        s0+=v0; q0+=v0*v0; s1+=v1; q1+=v1*v1;
    }
    float* p = g_part + blockIdx.x*1024;
    p[c0]=s0; p[c1]=s1; p[512+c0]=q0; p[512+c1]=q1;
}
__global__ void bn_final_kernel(){
    int c = threadIdx.x; // 512
    float s=0,q=0;
    for (int i=0;i<64;i++){ s += g_part[i*1024+c]; q += g_part[i*1024+512+c]; }
    float mu = s * (1.0f/RR);
    float var = q * (1.0f/RR) - mu*mu;
    g_stats[c] = mu;
    g_stats[512+c] = rsqrtf(var + EPS_BN);
}
__global__ void bn_apply_kernel(const float* __restrict__ x,
                                const float* __restrict__ gamma,
                                const float* __restrict__ beta){
    size_t i = (size_t)blockIdx.x*256 + threadIdx.x;
    int c = (int)(i & (DD-1));
    float v = (x[i]-g_stats[c])*g_stats[512+c]*gamma[c] + beta[c];
    g_xn[i] = v;
    g_h[i]  = v;
}

// ---------------- rms norm (row-wise over 512) ----------------
__global__ void rmsnorm_kernel(const float* __restrict__ x, const float* __restrict__ w,
                               float* __restrict__ y, long xs, long ys){
    __shared__ float red[8];
    int r = blockIdx.x, t = threadIdx.x;
    const float* xr = x + (size_t)r*xs;
    float a = xr[t], b = xr[t+256];
    float s = a*a + b*b;
    #pragma unroll
    for (int o=16;o;o>>=1) s += __shfl_xor_sync(~0u, s, o);
    if ((t&31)==0) red[t>>5]=s;
    __syncthreads();
    float tot = 0;
    #pragma unroll
    for (int i=0;i<8;i++) tot += red[i];
    float rs = rsqrtf(tot*(1.0f/DD) + EPS_RMS);
    float* yr = y + (size_t)r*ys;
    yr[t]     = a*rs*w[t];
    yr[t+256] = b*rs*w[t+256];
}

// ---------------- SGEMM: C[M,N] = A[M,K] @ B[K,N]  (128x128x8, 8x8/thread) ----
// EPI: 0 = store, 1 = C += result, 2 = sigmoid(result)
template<int EPI>
__global__ __launch_bounds__(256) void sgemm_kernel(const float* __restrict__ A,
                                                    const float* __restrict__ Bm,
                                                    float* __restrict__ C,
                                                    int M, int N, int K){
    __shared__ float As[8][128];
    __shared__ float Bs[8][128];
    int tid = threadIdx.x;
    int tx = tid & 15, ty = tid >> 4;
    const float* Ab = A + (size_t)blockIdx.y*128*K;
    const float* Bb = Bm + (size_t)blockIdx.x*128;
    int arow = tid >> 1;         // 0..127
    int acol = (tid & 1) * 4;    // 0 or 4
    int brow = tid >> 5;         // 0..7
    int bcol = (tid & 31) * 4;   // 0..124
    float acc[8][8];
    #pragma unroll
    for (int i=0;i<8;i++)
        #pragma unroll
        for (int j=0;j<8;j++) acc[i][j]=0.f;
    for (int k0=0;k0<K;k0+=8){
        float4 av = *reinterpret_cast<const float4*>(Ab + (size_t)arow*K + k0 + acol);
        As[acol+0][arow]=av.x; As[acol+1][arow]=av.y;
        As[acol+2][arow]=av.z; As[acol+3][arow]=av.w;
        float4 bv = *reinterpret_cast<const float4*>(Bb + (size_t)(k0+brow)*N + bcol);
        *reinterpret_cast<float4*>(&Bs[brow][bcol]) = bv;
        __syncthreads();
        #pragma unroll
        for (int kk=0;kk<8;kk++){
            float a[8], b[8];
            #pragma unroll
            for (int i=0;i<8;i++) a[i]=As[kk][ty*8+i];
            #pragma unroll
            for (int j=0;j<8;j++) b[j]=Bs[kk][tx*8+j];
            #pragma unroll
            for (int i=0;i<8;i++)
                #pragma unroll
                for (int j=0;j<8;j++) acc[i][j] += a[i]*b[j];
        }
        __syncthreads();
    }
    #pragma unroll
    for (int i=0;i<8;i++){
        size_t row = (size_t)blockIdx.y*128 + ty*8 + i;
        float* Cr = C + row*N + blockIdx.x*128 + tx*8;
        #pragma unroll
        for (int j=0;j<8;j++){
            float v = acc[i][j];
            if (EPI==1) v += Cr[j];
            if (EPI==2) v = 1.0f/(1.0f+expf(-v));
            Cr[j] = v;
        }
    }
}

// ---------------- gate projections (N=8 each, fused ig+fg) ----------------
__global__ void gates_kernel(const float* __restrict__ y,
                             const float* __restrict__ Wi, const float* __restrict__ bi,
                             const float* __restrict__ Wf, const float* __restrict__ bf){
    int warp = (blockIdx.x*blockDim.x + threadIdx.x) >> 5;
    int lane = threadIdx.x & 31;
    if (warp >= RR) return;
    const float* yr = y + (size_t)warp*DD;
    float si[8]={0,0,0,0,0,0,0,0}, sf[8]={0,0,0,0,0,0,0,0};
    for (int d=lane; d<DD; d+=32){
        float yv = yr[d];
        #pragma unroll
        for (int hh=0; hh<8; hh++){
            si[hh] += yv * Wi[d*HH+hh];
            sf[hh] += yv * Wf[d*HH+hh];
        }
    }
    #pragma unroll
    for (int hh=0; hh<8; hh++){
        #pragma unroll
        for (int o=16;o;o>>=1){
            si[hh]+=__shfl_xor_sync(~0u,si[hh],o);
            sf[hh]+=__shfl_xor_sync(~0u,sf[hh],o);
        }
    }
    if (lane==0){
        int b = warp >> 9, s = warp & 511;
        #pragma unroll
        for (int hh=0;hh<8;hh++){
            g_ig[((b*HH+hh)*SS)+s] = softcapf(si[hh]+bi[hh]);
            g_fg[((b*HH+hh)*SS)+s] = softcapf(sf[hh]+bf[hh]);
        }
    }
}

// ---------------- per-(b,h) prefix scan ----------------
__global__ void scan_kernel(){
    if (threadIdx.x != 0) return;
    int bh = blockIdx.x;
    const float* ig = g_ig + bh*SS;
    const float* fg = g_fg + bh*SS;
    float bc=0.f, cm=-1e30f;
    for (int s=0;s<SS;s++){
        bc += logsigf(fg[s]);
        float c = ig[s] - bc;
        cm = fmaxf(cm, c);
        g_bc[bh*SS+s] = bc;
        g_mv[bh*SS+s] = bc + cm;   // m[t]
    }
}

// ---------------- mLSTM attention ----------------
__global__ __launch_bounds__(64) void attn_kernel(){
    __shared__ float Ks[64*32];
    __shared__ float Vs[64*64];
    __shared__ float bs_s[64], ig_s[64];
    int bh = blockIdx.y; int b = bh >> 3; int h = bh & 7;
    int tt = blockIdx.x;
    int tid = threadIdx.x;
    int t = tt*64 + tid;
    const float* qp = g_q + ((size_t)(b*SS)+t)*QKD + h*DQK;
    float q[32];
    #pragma unroll
    for (int d=0;d<32;d++) q[d] = qp[d];
    float bt = g_bc[bh*SS + t];
    float mt = g_mv[bh*SS + t];
    float acc[64];
    #pragma unroll
    for (int j=0;j<64;j++) acc[j]=0.f;
    float ssum = 0.f;
    const float scale = 0.17677669529663687f;  // 1/sqrt(32)
    for (int st=0; st<=tt; st++){
        int s0 = st*64;
        for (int i=tid; i<64*32; i+=64){
            int rr=i>>5, cc=i&31;
            Ks[i] = g_k[((size_t)(b*SS)+s0+rr)*QKD + h*DQK + cc];
        }
        for (int i=tid; i<64*64; i+=64){
            int rr=i>>6, cc=i&63;
            Vs[i] = g_v[((size_t)(b*SS)+s0+rr)*VV + h*DV + cc];
        }
        bs_s[tid] = g_bc[bh*SS + s0 + tid];
        ig_s[tid] = g_ig[bh*SS + s0 + tid];
        __syncthreads();
        int smax = min(64, t - s0 + 1);
        for (int sl=0; sl<smax; sl++){
            float dot=0.f;
            #pragma unroll
            for (int d=0;d<32;d++) dot += q[d]*Ks[sl*32+d];
            float w = dot * scale * expf(bt - bs_s[sl] + ig_s[sl] - mt);
            ssum += w;
            const float* vr = &Vs[sl*64];
            #pragma unroll
            for (int j=0;j<64;j++) acc[j] += w*vr[j];
        }
        __syncthreads();
    }
    float nrm = fmaxf(fabsf(ssum), expf(-mt));
    float inv = 1.0f/(nrm + EPS_RMS);
    float* o = g_ht + ((size_t)(b*SS)+t)*VV + h*DV;
    #pragma unroll
    for (int j=0;j<64;j++) o[j] = acc[j]*inv;
}

// ---------------- per-head layer norm * mhn_w * og ----------------
__global__ void headnorm_kernel(const float* __restrict__ mhn){
    int r = blockIdx.x;
    int w = threadIdx.x >> 5;      // head
    int lane = threadIdx.x & 31;
    float* base = g_ht + (size_t)r*VV + w*DV;
    float e0 = base[lane], e1 = base[lane+32];
    float s = e0 + e1;
    #pragma unroll
    for (int o=16;o;o>>=1) s += __shfl_xor_sync(~0u,s,o);
    float mu = s * (1.0f/DV);
    float d0 = e0-mu, d1 = e1-mu;
    float v = d0*d0 + d1*d1;
    #pragma unroll
    for (int o=16;o;o>>=1) v += __shfl_xor_sync(~0u,v,o);
    float rs = rsqrtf(v*(1.0f/DV) + EPS_RMS);
    const float* ogb = g_og + (size_t)r*VV + w*DV;
    base[lane]    = d0*rs*mhn[w*DV+lane]   * ogb[lane];
    base[lane+32] = d1*rs*mhn[w*DV+lane+32]* ogb[lane+32];
}

// ---------------- silu(g)*u ----------------
__global__ void silu_mul_kernel(){
    size_t i = (size_t)blockIdx.x*256 + threadIdx.x;
    float g = g_gu1[i];
    float sig = 1.0f/(1.0f+expf(-g));
    g_gu1[i] = g*sig*g_gu2[i];
}

// ---------------- final heads ----------------
__global__ void bn1_kernel(const float* __restrict__ gamma, const float* __restrict__ beta){
    int c = threadIdx.x; // 512
    float v[16]; float mu=0.f;
    #pragma unroll
    for (int b=0;b<16;b++){ v[b]=g_last[b*DD+c]; mu+=v[b]; }
    mu *= (1.0f/16.0f);
    float var=0.f;
    #pragma unroll
    for (int b=0;b<16;b++){ float d=v[b]-mu; var+=d*d; }
    var *= (1.0f/16.0f);
    float rs = rsqrtf(var + EPS_BN);
    #pragma unroll
    for (int b=0;b<16;b++) g_last[b*DD+c] = (v[b]-mu)*rs*gamma[c] + beta[c];
}
__global__ void fc1_kernel(const float* __restrict__ W, const float* __restrict__ bias){
    __shared__ float xr[512];
    int b = blockIdx.x; int j = threadIdx.x; // 256
    xr[j]     = g_last[b*DD + j];
    xr[j+256] = g_last[b*DD + j + 256];
    __syncthreads();
    float s=0.f;
    #pragma unroll 8
    for (int k=0;k<512;k++) s += xr[k]*W[k*256+j];
    g_o1[b*256+j] = s + bias[j];
}
__global__ void bn2gelu_kernel(const float* __restrict__ gamma, const float* __restrict__ beta){
    int j = threadIdx.x; // 256
    float v[16]; float mu=0.f;
    #pragma unroll
    for (int b=0;b<16;b++){ v[b]=g_o1[b*256+j]; mu+=v[b]; }
    mu *= (1.0f/16.0f);
    float var=0.f;
    #pragma unroll
    for (int b=0;b<16;b++){ float d=v[b]-mu; var+=d*d; }
    var *= (1.0f/16.0f);
    float rs = rsqrtf(var + EPS_BN);
    #pragma unroll
    for (int b=0;b<16;b++){
        float t = (v[b]-mu)*rs*gamma[j] + beta[j];
        g_o1[b*256+j] = 0.5f*t*(1.0f + erff(t*0.7071067811865475f));
    }
}
__global__ void fc2_kernel(const float* __restrict__ W, const float* __restrict__ bias){
    __shared__ float red[256];
    int b = blockIdx.x; int j = threadIdx.x;
    red[j] = g_o1[b*256+j]*W[j];
    __syncthreads();
    for (int o=128;o;o>>=1){ if(j<o) red[j]+=red[j+o]; __syncthreads(); }
    if (j==0) g_o2[b] = red[0] + bias[0];
}
__global__ void res_out_kernel(const float* __restrict__ resW, const float* __restrict__ resb,
                               float* __restrict__ out){
    int warp = (blockIdx.x*blockDim.x + threadIdx.x) >> 5;
    int lane = threadIdx.x & 31;
    if (warp >= RR) return;
    const float* xr = g_xn + (size_t)warp*DD;
    float s=0.f;
    for (int d=lane; d<DD; d+=32) s += xr[d]*resW[d];
    #pragma unroll
    for (int o=16;o;o>>=1) s += __shfl_xor_sync(~0u,s,o);
    if (lane==0){
        float v = s + resb[0] + g_o2[warp>>9];
        out[warp] = fmaxf(v, 0.f);
    }
}

// ---------------- host driver ----------------
extern "C" void kernel_launch(void* const* d_in, const int* in_sizes, int n_in,
                              void* d_out, int out_size){
    const float* x        = (const float*)d_in[0];
    const float* bng      = (const float*)d_in[1];
    const float* bnb      = (const float*)d_in[2];
    const float* norm1_w  = (const float*)d_in[3];
    const float* norm2_w  = (const float*)d_in[4];
    const float* Wq       = (const float*)d_in[5];
    const float* Wk       = (const float*)d_in[6];
    const float* Wv       = (const float*)d_in[7];
    const float* Wog      = (const float*)d_in[8];
    const float* Wi       = (const float*)d_in[9];
    const float* bi       = (const float*)d_in[10];
    const float* Wf       = (const float*)d_in[11];
    const float* bf       = (const float*)d_in[12];
    const float* mhn_w    = (const float*)d_in[13];
    const float* Wout     = (const float*)d_in[14];
    const float* Wg       = (const float*)d_in[15];
    const float* Wu       = (const float*)d_in[16];
    const float* Wd       = (const float*)d_in[17];
    const float* fnorm_w  = (const float*)d_in[18];
    const float* bn1_g    = (const float*)d_in[19];
    const float* bn1_b    = (const float*)d_in[20];
    const float* fc1_W    = (const float*)d_in[21];
    const float* fc1_b    = (const float*)d_in[22];
    const float* bn2_g    = (const float*)d_in[23];
    const float* bn2_b    = (const float*)d_in[24];
    const float* fc2_W    = (const float*)d_in[25];
    const float* fc2_b    = (const float*)d_in[26];
    const float* res_W    = (const float*)d_in[27];
    const float* res_b    = (const float*)d_in[28];
    float* out = (float*)d_out;

    float *p_y,*p_q,*p_k,*p_v,*p_og,*p_ht,*p_h,*p_g1,*p_g2,*p_last;
    cudaGetSymbolAddress((void**)&p_y,  g_y);
    cudaGetSymbolAddress((void**)&p_q,  g_q);
    cudaGetSymbolAddress((void**)&p_k,  g_k);
    cudaGetSymbolAddress((void**)&p_v,  g_v);
    cudaGetSymbolAddress((void**)&p_og, g_og);
    cudaGetSymbolAddress((void**)&p_ht, g_ht);
    cudaGetSymbolAddress((void**)&p_h,  g_h);
    cudaGetSymbolAddress((void**)&p_g1, g_gu1);
    cudaGetSymbolAddress((void**)&p_g2, g_gu2);
    cudaGetSymbolAddress((void**)&p_last, g_last);

    // input batch norm -> g_xn, g_h
    bn_partial_kernel<<<64,256>>>(x);
    bn_final_kernel<<<1,512>>>();
    bn_apply_kernel<<<RR*DD/256,256>>>(x, bng, bnb);

    for (int l=0;l<LL;l++){
        const float* Wq_l = Wq + (size_t)l*DD*QKD;
        const float* Wk_l = Wk + (size_t)l*DD*QKD;
        const float* Wv_l = Wv + (size_t)l*DD*VV;
        const float* Wog_l= Wog+ (size_t)l*DD*VV;
        const float* Wi_l = Wi + (size_t)l*DD*HH;
        const float* Wf_l = Wf + (size_t)l*DD*HH;
        const float* Wout_l = Wout + (size_t)l*VV*DD;
        const float* Wg_l = Wg + (size_t)l*DD*FF;
        const float* Wu_l = Wu + (size_t)l*DD*FF;
        const float* Wd_l = Wd + (size_t)l*FF*DD;

        rmsnorm_kernel<<<RR,256>>>(p_h, norm1_w + l*DD, p_y, DD, DD);

        sgemm_kernel<0><<<dim3(QKD/128, RR/128),256>>>(p_y, Wq_l, p_q, RR, QKD, DD);
        sgemm_kernel<0><<<dim3(QKD/128, RR/128),256>>>(p_y, Wk_l, p_k, RR, QKD, DD);
        sgemm_kernel<0><<<dim3(VV/128,  RR/128),256>>>(p_y, Wv_l, p_v, RR, VV, DD);
        sgemm_kernel<2><<<dim3(VV/128,  RR/128),256>>>(p_y, Wog_l,p_og,RR, VV, DD);
        gates_kernel<<<RR/8,256>>>(p_y, Wi_l, bi + l*HH, Wf_l, bf + l*HH);
        scan_kernel<<<BB*HH,32>>>();

        attn_kernel<<<dim3(SS/64, BB*HH),64>>>();

        headnorm_kernel<<<RR,256>>>(mhn_w + l*VV);
        sgemm_kernel<1><<<dim3(DD/128, RR/128),256>>>(p_ht, Wout_l, p_h, RR, DD, VV);

        rmsnorm_kernel<<<RR,256>>>(p_h, norm2_w + l*DD, p_y, DD, DD);
        sgemm_kernel<0><<<dim3(FF/128, RR/128),256>>>(p_y, Wg_l, p_g1, RR, FF, DD);
        sgemm_kernel<0><<<dim3(FF/128, RR/128),256>>>(p_y, Wu_l, p_g2, RR, FF, DD);
        silu_mul_kernel<<<RR*FF/256,256>>>();
        sgemm_kernel<1><<<dim3(DD/128, RR/128),256>>>(p_g1, Wd_l, p_h, RR, DD, FF);
    }

    // final rms norm on last row of each batch -> g_last [16,512]
    rmsnorm_kernel<<<BB,256>>>(p_h + (size_t)(SS-1)*DD, fnorm_w, p_last,
                               (long)SS*DD, (long)DD);

    bn1_kernel<<<1,512>>>(bn1_g, bn1_b);
    fc1_kernel<<<BB,256>>>(fc1_W, fc1_b);
    bn2gelu_kernel<<<1,256>>>(bn2_g, bn2_b);
    fc2_kernel<<<BB,256>>>(fc2_W, fc2_b);
    res_out_kernel<<<RR/8,256>>>(res_W, res_b, out);
    (void)in_sizes; (void)n_in; (void)out_size;
}

// round 2
// speedup vs baseline: 1.7096x; 1.7096x over previous
#include <cuda_runtime.h>
#include <math.h>

// ---------------- problem constants ----------------
#define BB   16
#define SS   512
#define DD   512
#define LL   4
#define HH   8
#define QKD  256      // D/2
#define VV   512
#define FF   1408
#define RR   (BB*SS)      // 8192 rows
#define DQK  32
#define DV   64
#define EPS_RMS 1e-6f
#define EPS_BN  1e-5f
#define CAPV 15.0f

// ---------------- device scratch ----------------
__device__ float g_xn [RR*DD];
__device__ float g_h  [RR*DD];
__device__ float g_y  [RR*DD];
__device__ float g_q  [RR*QKD];
__device__ float g_k  [RR*QKD];
__device__ float g_v  [RR*VV];
__device__ float g_og [RR*VV];
__device__ float g_ht [RR*VV];
__device__ float g_ig [BB*HH*SS];
__device__ float g_fg [BB*HH*SS];
__device__ float g_bc [BB*HH*SS];
__device__ float g_mv [BB*HH*SS];
__device__ float g_gu1[RR*FF];
__device__ float g_gu2[RR*FF];
__device__ float g_part[64*1024];
__device__ float g_stats[1024];
__device__ float g_last[BB*DD];
__device__ float g_o1 [BB*256];
__device__ float g_o2 [BB];

__device__ __forceinline__ float softcapf(float x){ return CAPV * tanhf(x * (1.0f/CAPV)); }
__device__ __forceinline__ float logsigf(float x){ return fminf(x,0.f) - log1pf(expf(-fabsf(x))); }
__device__ __forceinline__ unsigned f2tf32(float x){
    unsigned u; asm("cvt.rna.tf32.f32 %0, %1;" : "=r"(u) : "f"(x)); return u;
}
__device__ __forceinline__ void mma_tf32(float* c, const unsigned* a, const unsigned* b){
    asm volatile("mma.sync.aligned.m16n8k8.row.col.f32.tf32.tf32.f32 "
        "{%0,%1,%2,%3}, {%4,%5,%6,%7}, {%8,%9}, {%0,%1,%2,%3};"
        : "+f"(c[0]), "+f"(c[1]), "+f"(c[2]), "+f"(c[3])
        : "r"(a[0]), "r"(a[1]), "r"(a[2]), "r"(a[3]), "r"(b[0]), "r"(b[1]));
}

// ---------------- input batch norm ----------------
__global__ void bn_partial_kernel(const float* __restrict__ x){
    int c0 = threadIdx.x, c1 = threadIdx.x + 256;
    float s0=0,s1=0,q0=0,q1=0;
    const float* base = x + (size_t)blockIdx.x * 128 * DD;
    for (int r=0;r<128;r++){
        float v0 = base[(size_t)r*DD + c0];
        float v1 = base[(size_t)r*DD + c1];
        s0+=v0; q0+=v0*v0; s1+=v1; q1+=v1*v1;
    }
    float* p = g_part + blockIdx.x*1024;
    p[c0]=s0; p[c1]=s1; p[512+c0]=q0; p[512+c1]=q1;
}
__global__ void bn_final_kernel(){
    int c = threadIdx.x; // 512
    float s=0,q=0;
    for (int i=0;i<64;i++){ s += g_part[i*1024+c]; q += g_part[i*1024+512+c]; }
    float mu = s * (1.0f/RR);
    float var = q * (1.0f/RR) - mu*mu;
    g_stats[c] = mu;
    g_stats[512+c] = rsqrtf(var + EPS_BN);
}
__global__ void bn_apply_kernel(const float* __restrict__ x,
                                const float* __restrict__ gamma,
                                const float* __restrict__ beta){
    size_t i = (size_t)blockIdx.x*256 + threadIdx.x;
    int c = (int)(i & (DD-1));
    float v = (x[i]-g_stats[c])*g_stats[512+c]*gamma[c] + beta[c];
    g_xn[i] = v;
    g_h[i]  = v;
}

// ---------------- rms norm ----------------
__global__ void rmsnorm_kernel(const float* __restrict__ x, const float* __restrict__ w,
                               float* __restrict__ y, long xs, long ys){
    __shared__ float red[8];
    int r = blockIdx.x, t = threadIdx.x;
    const float* xr = x + (size_t)r*xs;
    float a = xr[t], b = xr[t+256];
    float s = a*a + b*b;
    #pragma unroll
    for (int o=16;o;o>>=1) s += __shfl_xor_sync(~0u, s, o);
    if ((t&31)==0) red[t>>5]=s;
    __syncthreads();
    float tot = 0;
    #pragma unroll
    for (int i=0;i<8;i++) tot += red[i];
    float rs = rsqrtf(tot*(1.0f/DD) + EPS_RMS);
    float* yr = y + (size_t)r*ys;
    yr[t]     = a*rs*w[t];
    yr[t+256] = b*rs*w[t+256];
}

// ---------------- tf32 tensor-core GEMM ----------------
// C[M,N] = A[M,K] @ B[K,N]; block 128x128, K-tile 32, 8 warps, warp 64x32.
// EPI: 0 store, 1 C+=, 2 sigmoid, 3 C = silu(C)*acc
// Dual operand: blockIdx.z selects (B0,C0) or (B1,C1).
#define ASTRIDE 132
template<int EPI>
__global__ __launch_bounds__(256,1) void tgemm_kernel(
        const float* __restrict__ A,
        const float* __restrict__ B0, float* __restrict__ C0,
        const float* __restrict__ B1, float* __restrict__ C1,
        int N, int K){
    __shared__ unsigned As[32*ASTRIDE];
    __shared__ unsigned Bs[32*ASTRIDE];
    const float* Bm = (blockIdx.z == 0) ? B0 : B1;
    float* C = (blockIdx.z == 0) ? C0 : C1;
    const int tid = threadIdx.x;
    const int lane = tid & 31;
    const int wid = tid >> 5;
    const int g = lane >> 2, t = lane & 3;
    const int mb = (wid >> 2) * 64;
    const int nb = (wid & 3) * 32;
    const float* Ab = A + (size_t)blockIdx.y * 128 * K;
    const float* Bb = Bm + (size_t)blockIdx.x * 128;

    float acc[4][4][4];
    #pragma unroll
    for (int i=0;i<4;i++)
        #pragma unroll
        for (int j=0;j<4;j++)
            #pragma unroll
            for (int c=0;c<4;c++) acc[i][j][c]=0.f;

    float4 ra[4], rb[4];
    const int KT = K / 32;

    // prefetch tile 0
    #pragma unroll
    for (int i=0;i<4;i++){
        int idx = tid + i*256;
        int m = idx>>3, kq=(idx&7)*4;
        ra[i] = *reinterpret_cast<const float4*>(Ab + (size_t)m*K + kq);
        int kb = idx>>5, n=(idx&31)*4;
        rb[i] = *reinterpret_cast<const float4*>(Bb + (size_t)kb*N + n);
    }

    for (int kt=0; kt<KT; kt++){
        // store regs -> smem (cvt to tf32)
        #pragma unroll
        for (int i=0;i<4;i++){
            int idx = tid + i*256;
            int m = idx>>3, kq=(idx&7)*4;
            As[(kq+0)*ASTRIDE+m]=f2tf32(ra[i].x);
            As[(kq+1)*ASTRIDE+m]=f2tf32(ra[i].y);
            As[(kq+2)*ASTRIDE+m]=f2tf32(ra[i].z);
            As[(kq+3)*ASTRIDE+m]=f2tf32(ra[i].w);
            int kb = idx>>5, n=(idx&31)*4;
            Bs[kb*ASTRIDE+n+0]=f2tf32(rb[i].x);
            Bs[kb*ASTRIDE+n+1]=f2tf32(rb[i].y);
            Bs[kb*ASTRIDE+n+2]=f2tf32(rb[i].z);
            Bs[kb*ASTRIDE+n+3]=f2tf32(rb[i].w);
        }
        __syncthreads();
        if (kt+1 < KT){
            #pragma unroll
            for (int i=0;i<4;i++){
                int idx = tid + i*256;
                int m = idx>>3, kq=(idx&7)*4;
                ra[i] = *reinterpret_cast<const float4*>(Ab + (size_t)m*K + (kt+1)*32 + kq);
                int kb = idx>>5, n=(idx&31)*4;
                rb[i] = *reinterpret_cast<const float4*>(Bb + (size_t)((kt+1)*32+kb)*N + n);
            }
        }
        // compute 4 k-steps of 8
        #pragma unroll
        for (int kk=0;kk<4;kk++){
            int k0 = kk*8;
            unsigned af[4][4], bf[4][2];
            #pragma unroll
            for (int i=0;i<4;i++){
                int m0 = mb + i*16 + g;
                af[i][0] = As[(k0+t  )*ASTRIDE + m0    ];
                af[i][1] = As[(k0+t  )*ASTRIDE + m0 + 8];
                af[i][2] = As[(k0+t+4)*ASTRIDE + m0    ];
                af[i][3] = As[(k0+t+4)*ASTRIDE + m0 + 8];
            }
            #pragma unroll
            for (int j=0;j<4;j++){
                int n0 = nb + j*8 + g;
                bf[j][0] = Bs[(k0+t  )*ASTRIDE + n0];
                bf[j][1] = Bs[(k0+t+4)*ASTRIDE + n0];
            }
            #pragma unroll
            for (int i=0;i<4;i++)
                #pragma unroll
                for (int j=0;j<4;j++)
                    mma_tf32(acc[i][j], af[i], bf[j]);
        }
        __syncthreads();
    }

    // epilogue
    #pragma unroll
    for (int i=0;i<4;i++){
        #pragma unroll
        for (int j=0;j<4;j++){
            size_t row = (size_t)blockIdx.y*128 + mb + i*16 + g;
            size_t col = (size_t)blockIdx.x*128 + nb + j*8 + t*2;
            float* p0 = C + row*N + col;
            float* p1 = C + (row+8)*N + col;
            #pragma unroll
            for (int h=0; h<2; h++){
                float* p = h ? p1 : p0;
                float v0 = acc[i][j][h*2+0];
                float v1 = acc[i][j][h*2+1];
                if (EPI==0){ p[0]=v0; p[1]=v1; }
                else if (EPI==1){ p[0]+=v0; p[1]+=v1; }
                else if (EPI==2){
                    p[0] = 1.0f/(1.0f+expf(-v0));
                    p[1] = 1.0f/(1.0f+expf(-v1));
                } else {
                    float g0=p[0], g1v=p[1];
                    p[0] = g0*(1.0f/(1.0f+expf(-g0)))*v0;
                    p[1] = g1v*(1.0f/(1.0f+expf(-g1v)))*v1;
                }
            }
        }
    }
}

// ---------------- gate projections ----------------
__global__ void gates_kernel(const float* __restrict__ y,
                             const float* __restrict__ Wi, const float* __restrict__ bi,
                             const float* __restrict__ Wf, const float* __restrict__ bf){
    int warp = (blockIdx.x*blockDim.x + threadIdx.x) >> 5;
    int lane = threadIdx.x & 31;
    if (warp >= RR) return;
    const float* yr = y + (size_t)warp*DD;
    float si[8]={0,0,0,0,0,0,0,0}, sf[8]={0,0,0,0,0,0,0,0};
    for (int d=lane; d<DD; d+=32){
        float yv = yr[d];
        #pragma unroll
        for (int hh=0; hh<8; hh++){
            si[hh] += yv * Wi[d*HH+hh];
            sf[hh] += yv * Wf[d*HH+hh];
        }
    }
    #pragma unroll
    for (int hh=0; hh<8; hh++){
        #pragma unroll
        for (int o=16;o;o>>=1){
            si[hh]+=__shfl_xor_sync(~0u,si[hh],o);
            sf[hh]+=__shfl_xor_sync(~0u,sf[hh],o);
        }
    }
    if (lane==0){
        int b = warp >> 9, s = warp & 511;
        #pragma unroll
        for (int hh=0;hh<8;hh++){
            g_ig[((b*HH+hh)*SS)+s] = softcapf(si[hh]+bi[hh]);
            g_fg[((b*HH+hh)*SS)+s] = softcapf(sf[hh]+bf[hh]);
        }
    }
}

// ---------------- per-(b,h) prefix scan ----------------
__global__ void scan_kernel(){
    if (threadIdx.x != 0) return;
    int bh = blockIdx.x;
    const float* ig = g_ig + bh*SS;
    const float* fg = g_fg + bh*SS;
    float bc=0.f, cm=-1e30f;
    for (int s=0;s<SS;s++){
        bc += logsigf(fg[s]);
        float c = ig[s] - bc;
        cm = fmaxf(cm, c);
        g_bc[bh*SS+s] = bc;
        g_mv[bh*SS+s] = bc + cm;   // m[t]
    }
}

// ---------------- mLSTM attention ----------------
__global__ __launch_bounds__(64) void attn_kernel(){
    __shared__ float Ks[64*32];
    __shared__ float Vs[64*64];
    __shared__ float bs_s[64], ig_s[64];
    int bh = blockIdx.y; int b = bh >> 3; int h = bh & 7;
    int tt = blockIdx.x;
    int tid = threadIdx.x;
    int t = tt*64 + tid;
    const float* qp = g_q + ((size_t)(b*SS)+t)*QKD + h*DQK;
    float q[32];
    #pragma unroll
    for (int d=0;d<32;d++) q[d] = qp[d];
    float bt = g_bc[bh*SS + t];
    float mt = g_mv[bh*SS + t];
    float acc[64];
    #pragma unroll
    for (int j=0;j<64;j++) acc[j]=0.f;
    float ssum = 0.f;
    const float scale = 0.17677669529663687f;  // 1/sqrt(32)
    for (int st=0; st<=tt; st++){
        int s0 = st*64;
        for (int i=tid; i<64*32; i+=64){
            int rr=i>>5, cc=i&31;
            Ks[i] = g_k[((size_t)(b*SS)+s0+rr)*QKD + h*DQK + cc];
        }
        for (int i=tid; i<64*64; i+=64){
            int rr=i>>6, cc=i&63;
            Vs[i] = g_v[((size_t)(b*SS)+s0+rr)*VV + h*DV + cc];
        }
        bs_s[tid] = g_bc[bh*SS + s0 + tid];
        ig_s[tid] = g_ig[bh*SS + s0 + tid];
        __syncthreads();
        int smax = min(64, t - s0 + 1);
        for (int sl=0; sl<smax; sl++){
            float dot=0.f;
            #pragma unroll
            for (int d=0;d<32;d++) dot += q[d]*Ks[sl*32+d];
            float w = dot * scale * expf(bt - bs_s[sl] + ig_s[sl] - mt);
            ssum += w;
            const float* vr = &Vs[sl*64];
            #pragma unroll
            for (int j=0;j<64;j++) acc[j] += w*vr[j];
        }
        __syncthreads();
    }
    float nrm = fmaxf(fabsf(ssum), expf(-mt));
    float inv = 1.0f/(nrm + EPS_RMS);
    float* o = g_ht + ((size_t)(b*SS)+t)*VV + h*DV;
    #pragma unroll
    for (int j=0;j<64;j++) o[j] = acc[j]*inv;
}

// ---------------- per-head layer norm * mhn_w * og ----------------
__global__ void headnorm_kernel(const float* __restrict__ mhn){
    int r = blockIdx.x;
    int w = threadIdx.x >> 5;      // head
    int lane = threadIdx.x & 31;
    float* base = g_ht + (size_t)r*VV + w*DV;
    float e0 = base[lane], e1 = base[lane+32];
    float s = e0 + e1;
    #pragma unroll
    for (int o=16;o;o>>=1) s += __shfl_xor_sync(~0u,s,o);
    float mu = s * (1.0f/DV);
    float d0 = e0-mu, d1 = e1-mu;
    float v = d0*d0 + d1*d1;
    #pragma unroll
    for (int o=16;o;o>>=1) v += __shfl_xor_sync(~0u,v,o);
    float rs = rsqrtf(v*(1.0f/DV) + EPS_RMS);
    const float* ogb = g_og + (size_t)r*VV + w*DV;
    base[lane]    = d0*rs*mhn[w*DV+lane]   * ogb[lane];
    base[lane+32] = d1*rs*mhn[w*DV+lane+32]* ogb[lane+32];
}

// ---------------- final heads ----------------
__global__ void bn1_kernel(const float* __restrict__ gamma, const float* __restrict__ beta){
    int c = threadIdx.x; // 512
    float v[16]; float mu=0.f;
    #pragma unroll
    for (int b=0;b<16;b++){ v[b]=g_last[b*DD+c]; mu+=v[b]; }
    mu *= (1.0f/16.0f);
    float var=0.f;
    #pragma unroll
    for (int b=0;b<16;b++){ float d=v[b]-mu; var+=d*d; }
    var *= (1.0f/16.0f);
    float rs = rsqrtf(var + EPS_BN);
    #pragma unroll
    for (int b=0;b<16;b++) g_last[b*DD+c] = (v[b]-mu)*rs*gamma[c] + beta[c];
}
__global__ void fc1_kernel(const float* __restrict__ W, const float* __restrict__ bias){
    __shared__ float xr[512];
    int b = blockIdx.x; int j = threadIdx.x; // 256
    xr[j]     = g_last[b*DD + j];
    xr[j+256] = g_last[b*DD + j + 256];
    __syncthreads();
    float s=0.f;
    #pragma unroll 8
    for (int k=0;k<512;k++) s += xr[k]*W[k*256+j];
    g_o1[b*256+j] = s + bias[j];
}
__global__ void bn2gelu_kernel(const float* __restrict__ gamma, const float* __restrict__ beta){
    int j = threadIdx.x; // 256
    float v[16]; float mu=0.f;
    #pragma unroll
    for (int b=0;b<16;b++){ v[b]=g_o1[b*256+j]; mu+=v[b]; }
    mu *= (1.0f/16.0f);
    float var=0.f;
    #pragma unroll
    for (int b=0;b<16;b++){ float d=v[b]-mu; var+=d*d; }
    var *= (1.0f/16.0f);
    float rs = rsqrtf(var + EPS_BN);
    #pragma unroll
    for (int b=0;b<16;b++){
        float t = (v[b]-mu)*rs*gamma[j] + beta[j];
        g_o1[b*256+j] = 0.5f*t*(1.0f + erff(t*0.7071067811865475f));
    }
}
__global__ void fc2_kernel(const float* __restrict__ W, const float* __restrict__ bias){
    __shared__ float red[256];
    int b = blockIdx.x; int j = threadIdx.x;
    red[j] = g_o1[b*256+j]*W[j];
    __syncthreads();
    for (int o=128;o;o>>=1){ if(j<o) red[j]+=red[j+o]; __syncthreads(); }
    if (j==0) g_o2[b] = red[0] + bias[0];
}
__global__ void res_out_kernel(const float* __restrict__ resW, const float* __restrict__ resb,
                               float* __restrict__ out){
    int warp = (blockIdx.x*blockDim.x + threadIdx.x) >> 5;
    int lane = threadIdx.x & 31;
    if (warp >= RR) return;
    const float* xr = g_xn + (size_t)warp*DD;
    float s=0.f;
    for (int d=lane; d<DD; d+=32) s += xr[d]*resW[d];
    #pragma unroll
    for (int o=16;o;o>>=1) s += __shfl_xor_sync(~0u,s,o);
    if (lane==0){
        float v = s + resb[0] + g_o2[warp>>9];
        out[warp] = fmaxf(v, 0.f);
    }
}

// ---------------- host driver ----------------
extern "C" void kernel_launch(void* const* d_in, const int* in_sizes, int n_in,
                              void* d_out, int out_size){
    const float* x        = (const float*)d_in[0];
    const float* bng      = (const float*)d_in[1];
    const float* bnb      = (const float*)d_in[2];
    const float* norm1_w  = (const float*)d_in[3];
    const float* norm2_w  = (const float*)d_in[4];
    const float* Wq       = (const float*)d_in[5];
    const float* Wk       = (const float*)d_in[6];
    const float* Wv       = (const float*)d_in[7];
    const float* Wog      = (const float*)d_in[8];
    const float* Wi       = (const float*)d_in[9];
    const float* bi       = (const float*)d_in[10];
    const float* Wf       = (const float*)d_in[11];
    const float* bf       = (const float*)d_in[12];
    const float* mhn_w    = (const float*)d_in[13];
    const float* Wout     = (const float*)d_in[14];
    const float* Wg       = (const float*)d_in[15];
    const float* Wu       = (const float*)d_in[16];
    const float* Wd       = (const float*)d_in[17];
    const float* fnorm_w  = (const float*)d_in[18];
    const float* bn1_g    = (const float*)d_in[19];
    const float* bn1_b    = (const float*)d_in[20];
    const float* fc1_W    = (const float*)d_in[21];
    const float* fc1_b    = (const float*)d_in[22];
    const float* bn2_g    = (const float*)d_in[23];
    const float* bn2_b    = (const float*)d_in[24];
    const float* fc2_W    = (const float*)d_in[25];
    const float* fc2_b    = (const float*)d_in[26];
    const float* res_W    = (const float*)d_in[27];
    const float* res_b    = (const float*)d_in[28];
    float* out = (float*)d_out;

    float *p_y,*p_q,*p_k,*p_v,*p_og,*p_ht,*p_h,*p_g1,*p_g2,*p_last;
    cudaGetSymbolAddress((void**)&p_y,  g_y);
    cudaGetSymbolAddress((void**)&p_q,  g_q);
    cudaGetSymbolAddress((void**)&p_k,  g_k);
    cudaGetSymbolAddress((void**)&p_v,  g_v);
    cudaGetSymbolAddress((void**)&p_og, g_og);
    cudaGetSymbolAddress((void**)&p_ht, g_ht);
    cudaGetSymbolAddress((void**)&p_h,  g_h);
    cudaGetSymbolAddress((void**)&p_g1, g_gu1);
    cudaGetSymbolAddress((void**)&p_g2, g_gu2);
    cudaGetSymbolAddress((void**)&p_last, g_last);

    bn_partial_kernel<<<64,256>>>(x);
    bn_final_kernel<<<1,512>>>();
    bn_apply_kernel<<<RR*DD/256,256>>>(x, bng, bnb);

    for (int l=0;l<LL;l++){
        const float* Wq_l = Wq + (size_t)l*DD*QKD;
        const float* Wk_l = Wk + (size_t)l*DD*QKD;
        const float* Wv_l = Wv + (size_t)l*DD*VV;
        const float* Wog_l= Wog+ (size_t)l*DD*VV;
        const float* Wi_l = Wi + (size_t)l*DD*HH;
        const float* Wf_l = Wf + (size_t)l*DD*HH;
        const float* Wout_l = Wout + (size_t)l*VV*DD;
        const float* Wg_l = Wg + (size_t)l*DD*FF;
        const float* Wu_l = Wu + (size_t)l*DD*FF;
        const float* Wd_l = Wd + (size_t)l*FF*DD;

        rmsnorm_kernel<<<RR,256>>>(p_h, norm1_w + l*DD, p_y, DD, DD);

        // q & k in one dual launch (share A)
        tgemm_kernel<0><<<dim3(QKD/128, RR/128, 2),256>>>(p_y, Wq_l, p_q, Wk_l, p_k, QKD, DD);
        tgemm_kernel<0><<<dim3(VV/128,  RR/128, 1),256>>>(p_y, Wv_l, p_v, Wv_l, p_v, VV, DD);
        tgemm_kernel<2><<<dim3(VV/128,  RR/128, 1),256>>>(p_y, Wog_l,p_og,Wog_l,p_og,VV, DD);
        gates_kernel<<<RR/8,256>>>(p_y, Wi_l, bi + l*HH, Wf_l, bf + l*HH);
        scan_kernel<<<BB*HH,32>>>();

        attn_kernel<<<dim3(SS/64, BB*HH),64>>>();

        headnorm_kernel<<<RR,256>>>(mhn_w + l*VV);
        tgemm_kernel<1><<<dim3(DD/128, RR/128, 1),256>>>(p_ht, Wout_l, p_h, Wout_l, p_h, DD, VV);

        rmsnorm_kernel<<<RR,256>>>(p_h, norm2_w + l*DD, p_y, DD, DD);
        tgemm_kernel<0><<<dim3(FF/128, RR/128, 1),256>>>(p_y, Wg_l, p_g1, Wg_l, p_g1, FF, DD);
        tgemm_kernel<3><<<dim3(FF/128, RR/128, 1),256>>>(p_y, Wu_l, p_g1, Wu_l, p_g1, FF, DD);
        tgemm_kernel<1><<<dim3(DD/128, RR/128, 1),256>>>(p_g1, Wd_l, p_h, Wd_l, p_h, DD, FF);
    }

    rmsnorm_kernel<<<BB,256>>>(p_h + (size_t)(SS-1)*DD, fnorm_w, p_last,
                               (long)SS*DD, (long)DD);

    bn1_kernel<<<1,512>>>(bn1_g, bn1_b);
    fc1_kernel<<<BB,256>>>(fc1_W, fc1_b);
    bn2gelu_kernel<<<1,256>>>(bn2_g, bn2_b);
    fc2_kernel<<<BB,256>>>(fc2_W, fc2_b);
    res_out_kernel<<<RR/8,256>>>(res_W, res_b, out);
    (void)in_sizes; (void)n_in; (void)out_size;
}

// round 3
// speedup vs baseline: 2.2440x; 1.3126x over previous
#include <cuda_runtime.h>
#include <math.h>

// ---------------- problem constants ----------------
#define BB   16
#define SS   512
#define DD   512
#define LL   4
#define HH   8
#define QKD  256      // D/2
#define VV   512
#define FF   1408
#define RR   (BB*SS)      // 8192 rows
#define DQK  32
#define DV   64
#define EPS_RMS 1e-6f
#define EPS_BN  1e-5f
#define CAPV 15.0f

// ---------------- device scratch ----------------
__device__ float g_xn [RR*DD];
__device__ float g_h  [RR*DD];
__device__ float g_y  [RR*DD];
__device__ float g_q  [RR*QKD];
__device__ float g_k  [RR*QKD];
__device__ float g_v  [RR*VV];
__device__ float g_og [RR*VV];
__device__ float g_ht [RR*VV];
__device__ float g_ig [BB*HH*SS];
__device__ float g_fg [BB*HH*SS];
__device__ float g_bc [BB*HH*SS];
__device__ float g_mv [BB*HH*SS];
__device__ float g_gu1[RR*FF];
__device__ float g_gu2[RR*FF];
__device__ float g_part[64*1024];
__device__ float g_stats[1024];
__device__ float g_last[BB*DD];
__device__ float g_o1 [BB*256];
__device__ float g_o2 [BB];

__device__ __forceinline__ float softcapf(float x){ return CAPV * tanhf(x * (1.0f/CAPV)); }
__device__ __forceinline__ float logsigf(float x){ return fminf(x,0.f) - log1pf(expf(-fabsf(x))); }
__device__ __forceinline__ void mma_tf32(float* c, const unsigned* a, const unsigned* b){
    asm volatile("mma.sync.aligned.m16n8k8.row.col.f32.tf32.tf32.f32 "
        "{%0,%1,%2,%3}, {%4,%5,%6,%7}, {%8,%9}, {%0,%1,%2,%3};"
        : "+f"(c[0]), "+f"(c[1]), "+f"(c[2]), "+f"(c[3])
        : "r"(a[0]), "r"(a[1]), "r"(a[2]), "r"(a[3]), "r"(b[0]), "r"(b[1]));
}
__device__ __forceinline__ void cp16(void* smem_dst, const void* gsrc){
    unsigned s = (unsigned)__cvta_generic_to_shared(smem_dst);
    asm volatile("cp.async.cg.shared.global [%0], [%1], 16;" :: "r"(s), "l"(gsrc));
}
__device__ __forceinline__ void cp_commit(){ asm volatile("cp.async.commit_group;" ::: "memory"); }
template<int NN> __device__ __forceinline__ void cp_wait(){ asm volatile("cp.async.wait_group %0;" :: "n"(NN) : "memory"); }

// ---------------- input batch norm ----------------
__global__ void bn_partial_kernel(const float* __restrict__ x){
    int c0 = threadIdx.x, c1 = threadIdx.x + 256;
    float s0=0,s1=0,q0=0,q1=0;
    const float* base = x + (size_t)blockIdx.x * 128 * DD;
    for (int r=0;r<128;r++){
        float v0 = base[(size_t)r*DD + c0];
        float v1 = base[(size_t)r*DD + c1];
        s0+=v0; q0+=v0*v0; s1+=v1; q1+=v1*v1;
    }
    float* p = g_part + blockIdx.x*1024;
    p[c0]=s0; p[c1]=s1; p[512+c0]=q0; p[512+c1]=q1;
}
__global__ void bn_final_kernel(){
    int c = threadIdx.x; // 512
    float s=0,q=0;
    for (int i=0;i<64;i++){ s += g_part[i*1024+c]; q += g_part[i*1024+512+c]; }
    float mu = s * (1.0f/RR);
    float var = q * (1.0f/RR) - mu*mu;
    g_stats[c] = mu;
    g_stats[512+c] = rsqrtf(var + EPS_BN);
}
__global__ void bn_apply_kernel(const float* __restrict__ x,
                                const float* __restrict__ gamma,
                                const float* __restrict__ beta){
    size_t i = (size_t)blockIdx.x*256 + threadIdx.x;
    int c = (int)(i & (DD-1));
    float v = (x[i]-g_stats[c])*g_stats[512+c]*gamma[c] + beta[c];
    g_xn[i] = v;
    g_h[i]  = v;
}

// ---------------- rms norm ----------------
__global__ void rmsnorm_kernel(const float* __restrict__ x, const float* __restrict__ w,
                               float* __restrict__ y, long xs, long ys){
    __shared__ float red[8];
    int r = blockIdx.x, t = threadIdx.x;
    const float* xr = x + (size_t)r*xs;
    float a = xr[t], b = xr[t+256];
    float s = a*a + b*b;
    #pragma unroll
    for (int o=16;o;o>>=1) s += __shfl_xor_sync(~0u, s, o);
    if ((t&31)==0) red[t>>5]=s;
    __syncthreads();
    float tot = 0;
    #pragma unroll
    for (int i=0;i<8;i++) tot += red[i];
    float rs = rsqrtf(tot*(1.0f/DD) + EPS_RMS);
    float* yr = y + (size_t)r*ys;
    yr[t]     = a*rs*w[t];
    yr[t+256] = b*rs*w[t+256];
}

// ---------------- tf32 tensor-core GEMM v3 ----------------
// C[M,N] = A[M,K] @ B[K,N]; block 128x128, 4 warps of 64x64, K-tile 32,
// cp.async double buffer, raw fp32 fed to tf32 MMA (HW truncation).
// EPI: 0 store, 1 C+=, 2 sigmoid, 3 C = silu(C)*acc
#define APAD 36
#define BPAD 132
#define ASZ  (128*APAD)
#define BSZ  (32*BPAD)
#define TG_SMEM ((2*ASZ + 2*BSZ)*4)

template<int EPI>
__global__ __launch_bounds__(128) void tgemm_kernel(
        const float* __restrict__ A,
        const float* __restrict__ B0, float* __restrict__ C0,
        const float* __restrict__ B1, float* __restrict__ C1,
        int N, int K){
    extern __shared__ float sm[];
    float* As = sm;             // [2][ASZ]
    float* Bs = sm + 2*ASZ;     // [2][BSZ]
    const float* Bm = (blockIdx.z == 0) ? B0 : B1;
    float* C = (blockIdx.z == 0) ? C0 : C1;
    const int tid = threadIdx.x;
    const int lane = tid & 31;
    const int wid = tid >> 5;
    const int g = lane >> 2, t = lane & 3;
    const int mw = (wid >> 1) * 64;
    const int nw = (wid & 1) * 64;
    const float* Ab = A + (size_t)blockIdx.y * 128 * K;
    const float* Bb = Bm + (size_t)blockIdx.x * 128;

    float acc[4][8][4];
    #pragma unroll
    for (int i=0;i<4;i++)
        #pragma unroll
        for (int j=0;j<8;j++)
            #pragma unroll
            for (int c=0;c<4;c++) acc[i][j][c]=0.f;

    const int KT = K / 32;

    // tile loader: 1024 A-chunks + 1024 B-chunks of 16B, 8+8 per thread
    #define LOAD_TILE(kt, buf) do {                                           \
        float* Ad = As + (buf)*ASZ;                                           \
        float* Bd = Bs + (buf)*BSZ;                                           \
        _Pragma("unroll")                                                     \
        for (int ii=0; ii<8; ii++){                                           \
            int idx = tid + ii*128;                                           \
            int m = idx >> 3, c = idx & 7;                                    \
            cp16(Ad + m*APAD + c*4, Ab + (size_t)m*K + (kt)*32 + c*4);        \
        }                                                                     \
        _Pragma("unroll")                                                     \
        for (int ii=0; ii<8; ii++){                                           \
            int idx = tid + ii*128;                                           \
            int kr = idx >> 5, c = idx & 31;                                  \
            cp16(Bd + kr*BPAD + c*4, Bb + (size_t)((kt)*32+kr)*N + c*4);      \
        }                                                                     \
    } while(0)

    LOAD_TILE(0, 0);
    cp_commit();

    for (int kt=0; kt<KT; kt++){
        int buf = kt & 1;
        if (kt+1 < KT){
            LOAD_TILE(kt+1, buf^1);
            cp_commit();
            cp_wait<1>();
        } else {
            cp_wait<0>();
        }
        __syncthreads();
        const float* Ac = As + buf*ASZ;
        const float* Bc = Bs + buf*BSZ;
        #pragma unroll
        for (int ks=0; ks<4; ks++){
            int k0 = ks*8;
            unsigned af[4][4], bf[8][2];
            #pragma unroll
            for (int i=0;i<4;i++){
                int m0 = mw + i*16 + g;
                af[i][0] = __float_as_uint(Ac[(size_t)m0*APAD + k0 + t]);
                af[i][1] = __float_as_uint(Ac[(size_t)(m0+8)*APAD + k0 + t]);
                af[i][2] = __float_as_uint(Ac[(size_t)m0*APAD + k0 + t + 4]);
                af[i][3] = __float_as_uint(Ac[(size_t)(m0+8)*APAD + k0 + t + 4]);
            }
            #pragma unroll
            for (int j=0;j<8;j++){
                int n0 = nw + j*8 + g;
                bf[j][0] = __float_as_uint(Bc[(size_t)(k0+t)*BPAD + n0]);
                bf[j][1] = __float_as_uint(Bc[(size_t)(k0+t+4)*BPAD + n0]);
            }
            #pragma unroll
            for (int i=0;i<4;i++)
                #pragma unroll
                for (int j=0;j<8;j++)
                    mma_tf32(acc[i][j], af[i], bf[j]);
        }
        __syncthreads();
    }

    // epilogue
    #pragma unroll
    for (int i=0;i<4;i++){
        #pragma unroll
        for (int j=0;j<8;j++){
            size_t row = (size_t)blockIdx.y*128 + mw + i*16 + g;
            size_t col = (size_t)blockIdx.x*128 + nw + j*8 + t*2;
            float* p0 = C + row*N + col;
            float* p1 = C + (row+8)*N + col;
            #pragma unroll
            for (int h=0; h<2; h++){
                float* p = h ? p1 : p0;
                float v0 = acc[i][j][h*2+0];
                float v1 = acc[i][j][h*2+1];
                if (EPI==0){ p[0]=v0; p[1]=v1; }
                else if (EPI==1){ p[0]+=v0; p[1]+=v1; }
                else if (EPI==2){
                    p[0] = 1.0f/(1.0f+expf(-v0));
                    p[1] = 1.0f/(1.0f+expf(-v1));
                } else {
                    float g0=p[0], g1v=p[1];
                    p[0] = g0*(1.0f/(1.0f+expf(-g0)))*v0;
                    p[1] = g1v*(1.0f/(1.0f+expf(-g1v)))*v1;
                }
            }
        }
    }
    #undef LOAD_TILE
}

// ---------------- gate projections ----------------
__global__ void gates_kernel(const float* __restrict__ y,
                             const float* __restrict__ Wi, const float* __restrict__ bi,
                             const float* __restrict__ Wf, const float* __restrict__ bf){
    int warp = (blockIdx.x*blockDim.x + threadIdx.x) >> 5;
    int lane = threadIdx.x & 31;
    if (warp >= RR) return;
    const float* yr = y + (size_t)warp*DD;
    float si[8]={0,0,0,0,0,0,0,0}, sf[8]={0,0,0,0,0,0,0,0};
    for (int d=lane; d<DD; d+=32){
        float yv = yr[d];
        #pragma unroll
        for (int hh=0; hh<8; hh++){
            si[hh] += yv * Wi[d*HH+hh];
            sf[hh] += yv * Wf[d*HH+hh];
        }
    }
    #pragma unroll
    for (int hh=0; hh<8; hh++){
        #pragma unroll
        for (int o=16;o;o>>=1){
            si[hh]+=__shfl_xor_sync(~0u,si[hh],o);
            sf[hh]+=__shfl_xor_sync(~0u,sf[hh],o);
        }
    }
    if (lane==0){
        int b = warp >> 9, s = warp & 511;
        #pragma unroll
        for (int hh=0;hh<8;hh++){
            g_ig[((b*HH+hh)*SS)+s] = softcapf(si[hh]+bi[hh]);
            g_fg[((b*HH+hh)*SS)+s] = softcapf(sf[hh]+bf[hh]);
        }
    }
}

// ---------------- per-(b,h) prefix scan ----------------
__global__ void scan_kernel(){
    if (threadIdx.x != 0) return;
    int bh = blockIdx.x;
    const float* ig = g_ig + bh*SS;
    const float* fg = g_fg + bh*SS;
    float bc=0.f, cm=-1e30f;
    for (int s=0;s<SS;s++){
        bc += logsigf(fg[s]);
        float c = ig[s] - bc;
        cm = fmaxf(cm, c);
        g_bc[bh*SS+s] = bc;
        g_mv[bh*SS+s] = bc + cm;   // m[t]
    }
}

// ---------------- mLSTM attention (float4 vectorized) ----------------
__global__ __launch_bounds__(64) void attn_kernel(){
    __shared__ float4 Ks[64*8];   // 64 rows x 32 floats
    __shared__ float4 Vs[64*16];  // 64 rows x 64 floats
    __shared__ float bs_s[64], ig_s[64];
    int bh = blockIdx.y; int b = bh >> 3; int h = bh & 7;
    int tt = blockIdx.x;
    int tid = threadIdx.x;
    int t = tt*64 + tid;
    const float4* qp = (const float4*)(g_q + ((size_t)(b*SS)+t)*QKD + h*DQK);
    float4 q4[8];
    #pragma unroll
    for (int d=0;d<8;d++) q4[d] = qp[d];
    float bt = g_bc[bh*SS + t];
    float mt = g_mv[bh*SS + t];
    float4 acc[16];
    #pragma unroll
    for (int j=0;j<16;j++) acc[j] = make_float4(0.f,0.f,0.f,0.f);
    float ssum = 0.f;
    const float scale = 0.17677669529663687f;  // 1/sqrt(32)
    for (int st=0; st<=tt; st++){
        int s0 = st*64;
        #pragma unroll
        for (int ii=0; ii<8; ii++){
            int idx = tid + ii*64;       // 0..511
            int rr = idx >> 3, cc = idx & 7;
            Ks[idx] = *(const float4*)(g_k + ((size_t)(b*SS)+s0+rr)*QKD + h*DQK + cc*4);
        }
        #pragma unroll
        for (int ii=0; ii<16; ii++){
            int idx = tid + ii*64;       // 0..1023
            int rr = idx >> 4, cc = idx & 15;
            Vs[idx] = *(const float4*)(g_v + ((size_t)(b*SS)+s0+rr)*VV + h*DV + cc*4);
        }
        bs_s[tid] = g_bc[bh*SS + s0 + tid];
        ig_s[tid] = g_ig[bh*SS + s0 + tid];
        __syncthreads();
        int smax = min(64, t - s0 + 1);
        for (int sl=0; sl<smax; sl++){
            const float4* kp = &Ks[sl*8];
            float dot=0.f;
            #pragma unroll
            for (int d=0;d<8;d++){
                float4 kv = kp[d];
                dot += q4[d].x*kv.x + q4[d].y*kv.y + q4[d].z*kv.z + q4[d].w*kv.w;
            }
            float w = dot * scale * __expf(bt - bs_s[sl] + ig_s[sl] - mt);
            ssum += w;
            const float4* vp = &Vs[sl*16];
            #pragma unroll
            for (int j=0;j<16;j++){
                float4 vv = vp[j];
                acc[j].x += w*vv.x; acc[j].y += w*vv.y;
                acc[j].z += w*vv.z; acc[j].w += w*vv.w;
            }
        }
        __syncthreads();
    }
    float nrm = fmaxf(fabsf(ssum), __expf(-mt));
    float inv = 1.0f/(nrm + EPS_RMS);
    float4* o = (float4*)(g_ht + ((size_t)(b*SS)+t)*VV + h*DV);
    #pragma unroll
    for (int j=0;j<16;j++){
        float4 a = acc[j];
        o[j] = make_float4(a.x*inv, a.y*inv, a.z*inv, a.w*inv);
    }
}

// ---------------- per-head layer norm * mhn_w * og ----------------
__global__ void headnorm_kernel(const float* __restrict__ mhn){
    int r = blockIdx.x;
    int w = threadIdx.x >> 5;      // head
    int lane = threadIdx.x & 31;
    float* base = g_ht + (size_t)r*VV + w*DV;
    float e0 = base[lane], e1 = base[lane+32];
    float s = e0 + e1;
    #pragma unroll
    for (int o=16;o;o>>=1) s += __shfl_xor_sync(~0u,s,o);
    float mu = s * (1.0f/DV);
    float d0 = e0-mu, d1 = e1-mu;
    float v = d0*d0 + d1*d1;
    #pragma unroll
    for (int o=16;o;o>>=1) v += __shfl_xor_sync(~0u,v,o);
    float rs = rsqrtf(v*(1.0f/DV) + EPS_RMS);
    const float* ogb = g_og + (size_t)r*VV + w*DV;
    base[lane]    = d0*rs*mhn[w*DV+lane]   * ogb[lane];
    base[lane+32] = d1*rs*mhn[w*DV+lane+32]* ogb[lane+32];
}

// ---------------- final heads ----------------
__global__ void bn1_kernel(const float* __restrict__ gamma, const float* __restrict__ beta){
    int c = threadIdx.x; // 512
    float v[16]; float mu=0.f;
    #pragma unroll
    for (int b=0;b<16;b++){ v[b]=g_last[b*DD+c]; mu+=v[b]; }
    mu *= (1.0f/16.0f);
    float var=0.f;
    #pragma unroll
    for (int b=0;b<16;b++){ float d=v[b]-mu; var+=d*d; }
    var *= (1.0f/16.0f);
    float rs = rsqrtf(var + EPS_BN);
    #pragma unroll
    for (int b=0;b<16;b++) g_last[b*DD+c] = (v[b]-mu)*rs*gamma[c] + beta[c];
}
__global__ void fc1_kernel(const float* __restrict__ W, const float* __restrict__ bias){
    __shared__ float xr[512];
    int b = blockIdx.x; int j = threadIdx.x; // 256
    xr[j]     = g_last[b*DD + j];
    xr[j+256] = g_last[b*DD + j + 256];
    __syncthreads();
    float s=0.f;
    #pragma unroll 8
    for (int k=0;k<512;k++) s += xr[k]*W[k*256+j];
    g_o1[b*256+j] = s + bias[j];
}
__global__ void bn2gelu_kernel(const float* __restrict__ gamma, const float* __restrict__ beta){
    int j = threadIdx.x; // 256
    float v[16]; float mu=0.f;
    #pragma unroll
    for (int b=0;b<16;b++){ v[b]=g_o1[b*256+j]; mu+=v[b]; }
    mu *= (1.0f/16.0f);
    float var=0.f;
    #pragma unroll
    for (int b=0;b<16;b++){ float d=v[b]-mu; var+=d*d; }
    var *= (1.0f/16.0f);
    float rs = rsqrtf(var + EPS_BN);
    #pragma unroll
    for (int b=0;b<16;b++){
        float t = (v[b]-mu)*rs*gamma[j] + beta[j];
        g_o1[b*256+j] = 0.5f*t*(1.0f + erff(t*0.7071067811865475f));
    }
}
__global__ void fc2_kernel(const float* __restrict__ W, const float* __restrict__ bias){
    __shared__ float red[256];
    int b = blockIdx.x; int j = threadIdx.x;
    red[j] = g_o1[b*256+j]*W[j];
    __syncthreads();
    for (int o=128;o;o>>=1){ if(j<o) red[j]+=red[j+o]; __syncthreads(); }
    if (j==0) g_o2[b] = red[0] + bias[0];
}
__global__ void res_out_kernel(const float* __restrict__ resW, const float* __restrict__ resb,
                               float* __restrict__ out){
    int warp = (blockIdx.x*blockDim.x + threadIdx.x) >> 5;
    int lane = threadIdx.x & 31;
    if (warp >= RR) return;
    const float* xr = g_xn + (size_t)warp*DD;
    float s=0.f;
    for (int d=lane; d<DD; d+=32) s += xr[d]*resW[d];
    #pragma unroll
    for (int o=16;o;o>>=1) s += __shfl_xor_sync(~0u,s,o);
    if (lane==0){
        float v = s + resb[0] + g_o2[warp>>9];
        out[warp] = fmaxf(v, 0.f);
    }
}

// ---------------- host driver ----------------
extern "C" void kernel_launch(void* const* d_in, const int* in_sizes, int n_in,
                              void* d_out, int out_size){
    const float* x        = (const float*)d_in[0];
    const float* bng      = (const float*)d_in[1];
    const float* bnb      = (const float*)d_in[2];
    const float* norm1_w  = (const float*)d_in[3];
    const float* norm2_w  = (const float*)d_in[4];
    const float* Wq       = (const float*)d_in[5];
    const float* Wk       = (const float*)d_in[6];
    const float* Wv       = (const float*)d_in[7];
    const float* Wog      = (const float*)d_in[8];
    const float* Wi       = (const float*)d_in[9];
    const float* bi       = (const float*)d_in[10];
    const float* Wf       = (const float*)d_in[11];
    const float* bf       = (const float*)d_in[12];
    const float* mhn_w    = (const float*)d_in[13];
    const float* Wout     = (const float*)d_in[14];
    const float* Wg       = (const float*)d_in[15];
    const float* Wu       = (const float*)d_in[16];
    const float* Wd       = (const float*)d_in[17];
    const float* fnorm_w  = (const float*)d_in[18];
    const float* bn1_g    = (const float*)d_in[19];
    const float* bn1_b    = (const float*)d_in[20];
    const float* fc1_W    = (const float*)d_in[21];
    const float* fc1_b    = (const float*)d_in[22];
    const float* bn2_g    = (const float*)d_in[23];
    const float* bn2_b    = (const float*)d_in[24];
    const float* fc2_W    = (const float*)d_in[25];
    const float* fc2_b    = (const float*)d_in[26];
    const float* res_W    = (const float*)d_in[27];
    const float* res_b    = (const float*)d_in[28];
    float* out = (float*)d_out;

    float *p_y,*p_q,*p_k,*p_v,*p_og,*p_ht,*p_h,*p_g1,*p_g2,*p_last;
    cudaGetSymbolAddress((void**)&p_y,  g_y);
    cudaGetSymbolAddress((void**)&p_q,  g_q);
    cudaGetSymbolAddress((void**)&p_k,  g_k);
    cudaGetSymbolAddress((void**)&p_v,  g_v);
    cudaGetSymbolAddress((void**)&p_og, g_og);
    cudaGetSymbolAddress((void**)&p_ht, g_ht);
    cudaGetSymbolAddress((void**)&p_h,  g_h);
    cudaGetSymbolAddress((void**)&p_g1, g_gu1);
    cudaGetSymbolAddress((void**)&p_g2, g_gu2);
    cudaGetSymbolAddress((void**)&p_last, g_last);

    cudaFuncSetAttribute(tgemm_kernel<0>, cudaFuncAttributeMaxDynamicSharedMemorySize, TG_SMEM);
    cudaFuncSetAttribute(tgemm_kernel<1>, cudaFuncAttributeMaxDynamicSharedMemorySize, TG_SMEM);
    cudaFuncSetAttribute(tgemm_kernel<2>, cudaFuncAttributeMaxDynamicSharedMemorySize, TG_SMEM);
    cudaFuncSetAttribute(tgemm_kernel<3>, cudaFuncAttributeMaxDynamicSharedMemorySize, TG_SMEM);

    bn_partial_kernel<<<64,256>>>(x);
    bn_final_kernel<<<1,512>>>();
    bn_apply_kernel<<<RR*DD/256,256>>>(x, bng, bnb);

    for (int l=0;l<LL;l++){
        const float* Wq_l = Wq + (size_t)l*DD*QKD;
        const float* Wk_l = Wk + (size_t)l*DD*QKD;
        const float* Wv_l = Wv + (size_t)l*DD*VV;
        const float* Wog_l= Wog+ (size_t)l*DD*VV;
        const float* Wi_l = Wi + (size_t)l*DD*HH;
        const float* Wf_l = Wf + (size_t)l*DD*HH;
        const float* Wout_l = Wout + (size_t)l*VV*DD;
        const float* Wg_l = Wg + (size_t)l*DD*FF;
        const float* Wu_l = Wu + (size_t)l*DD*FF;
        const float* Wd_l = Wd + (size_t)l*FF*DD;

        rmsnorm_kernel<<<RR,256>>>(p_h, norm1_w + l*DD, p_y, DD, DD);

        tgemm_kernel<0><<<dim3(QKD/128, RR/128, 2),128,TG_SMEM>>>(p_y, Wq_l, p_q, Wk_l, p_k, QKD, DD);
        tgemm_kernel<0><<<dim3(VV/128,  RR/128, 1),128,TG_SMEM>>>(p_y, Wv_l, p_v, Wv_l, p_v, VV, DD);
        tgemm_kernel<2><<<dim3(VV/128,  RR/128, 1),128,TG_SMEM>>>(p_y, Wog_l,p_og,Wog_l,p_og,VV, DD);
        gates_kernel<<<RR/8,256>>>(p_y, Wi_l, bi + l*HH, Wf_l, bf + l*HH);
        scan_kernel<<<BB*HH,32>>>();

        attn_kernel<<<dim3(SS/64, BB*HH),64>>>();

        headnorm_kernel<<<RR,256>>>(mhn_w + l*VV);
        tgemm_kernel<1><<<dim3(DD/128, RR/128, 1),128,TG_SMEM>>>(p_ht, Wout_l, p_h, Wout_l, p_h, DD, VV);

        rmsnorm_kernel<<<RR,256>>>(p_h, norm2_w + l*DD, p_y, DD, DD);
        tgemm_kernel<0><<<dim3(FF/128, RR/128, 1),128,TG_SMEM>>>(p_y, Wg_l, p_g1, Wg_l, p_g1, FF, DD);
        tgemm_kernel<3><<<dim3(FF/128, RR/128, 1),128,TG_SMEM>>>(p_y, Wu_l, p_g1, Wu_l, p_g1, FF, DD);
        tgemm_kernel<1><<<dim3(DD/128, RR/128, 1),128,TG_SMEM>>>(p_g1, Wd_l, p_h, Wd_l, p_h, DD, FF);
    }

    rmsnorm_kernel<<<BB,256>>>(p_h + (size_t)(SS-1)*DD, fnorm_w, p_last,
                               (long)SS*DD, (long)DD);

    bn1_kernel<<<1,512>>>(bn1_g, bn1_b);
    fc1_kernel<<<BB,256>>>(fc1_W, fc1_b);
    bn2gelu_kernel<<<1,256>>>(bn2_g, bn2_b);
    fc2_kernel<<<BB,256>>>(fc2_W, fc2_b);
    res_out_kernel<<<RR/8,256>>>(res_W, res_b, out);
    (void)in_sizes; (void)n_in; (void)out_size;
}

// round 4
// speedup vs baseline: 3.0890x; 1.3766x over previous
#include <cuda_runtime.h>
#include <cuda_fp16.h>
#include <math.h>

// ---------------- problem constants ----------------
#define BB   16
#define SS   512
#define DD   512
#define LL   4
#define HH   8
#define QKD  256      // D/2
#define VV   512
#define FF   1408
#define RR   (BB*SS)      // 8192 rows
#define DQK  32
#define DV   64
#define EPS_RMS 1e-6f
#define EPS_BN  1e-5f
#define CAPV 15.0f

// weight half-buffer offsets (element counts, all layers concatenated)
#define OFF_WQ   0L
#define OFF_WK   524288L
#define OFF_WV   1048576L
#define OFF_WOG  2097152L
#define OFF_WOUT 3145728L
#define OFF_WG   4194304L
#define OFF_WU   7077888L
#define OFF_WD   9961472L
#define TOTW     12845056L

// ---------------- device scratch ----------------
__device__ float g_xn [RR*DD];
__device__ float g_h  [RR*DD];
__device__ float g_q  [RR*QKD];
__device__ float g_k  [RR*QKD];
__device__ float g_v  [RR*VV];
__device__ float g_og [RR*VV];
__device__ float g_ht [RR*VV];
__device__ float g_ig [BB*HH*SS];
__device__ float g_fg [BB*HH*SS];
__device__ float g_bc [BB*HH*SS];
__device__ float g_mv [BB*HH*SS];
__device__ float g_gu1[RR*FF];
__device__ float g_part[64*1024];
__device__ float g_stats[1024];
__device__ float g_last[BB*DD];
__device__ float g_o1 [BB*256];
__device__ float g_o2 [BB];

__device__ __half g_wh  [TOTW];      // fp16 weights
__device__ __half g_yh  [RR*DD];     // fp16 rms-normed activations
__device__ __half g_hth [RR*VV];     // fp16 headnorm output
__device__ __half g_g1h [RR*FF];     // fp16 silu(g)*u

__device__ __forceinline__ float softcapf(float x){ return CAPV * tanhf(x * (1.0f/CAPV)); }
__device__ __forceinline__ float logsigf(float x){ return fminf(x,0.f) - log1pf(expf(-fabsf(x))); }

__device__ __forceinline__ void cp16(void* smem_dst, const void* gsrc){
    unsigned s = (unsigned)__cvta_generic_to_shared(smem_dst);
    asm volatile("cp.async.cg.shared.global [%0], [%1], 16;" :: "r"(s), "l"(gsrc));
}
__device__ __forceinline__ void cp_commit(){ asm volatile("cp.async.commit_group;" ::: "memory"); }
template<int NN> __device__ __forceinline__ void cp_wait(){ asm volatile("cp.async.wait_group %0;" :: "n"(NN) : "memory"); }

__device__ __forceinline__ void mma_f16(float* c, const unsigned* a, const unsigned* b){
    asm volatile("mma.sync.aligned.m16n8k16.row.col.f32.f16.f16.f32 "
        "{%0,%1,%2,%3}, {%4,%5,%6,%7}, {%8,%9}, {%0,%1,%2,%3};"
        : "+f"(c[0]), "+f"(c[1]), "+f"(c[2]), "+f"(c[3])
        : "r"(a[0]), "r"(a[1]), "r"(a[2]), "r"(a[3]), "r"(b[0]), "r"(b[1]));
}
__device__ __forceinline__ void ldsm4(unsigned& r0, unsigned& r1, unsigned& r2, unsigned& r3, unsigned addr){
    asm volatile("ldmatrix.sync.aligned.m8n8.x4.shared.b16 {%0,%1,%2,%3}, [%4];"
        : "=r"(r0), "=r"(r1), "=r"(r2), "=r"(r3) : "r"(addr));
}
__device__ __forceinline__ void ldsm4t(unsigned& r0, unsigned& r1, unsigned& r2, unsigned& r3, unsigned addr){
    asm volatile("ldmatrix.sync.aligned.m8n8.x4.trans.shared.b16 {%0,%1,%2,%3}, [%4];"
        : "=r"(r0), "=r"(r1), "=r"(r2), "=r"(r3) : "r"(addr));
}

// ---------------- bn partial + weight fp32->fp16 conversion (fused launch) ----
__global__ void bnpart_conv_kernel(const float* __restrict__ x,
        const float* __restrict__ Wq, const float* __restrict__ Wk,
        const float* __restrict__ Wv, const float* __restrict__ Wog,
        const float* __restrict__ Wout, const float* __restrict__ Wg,
        const float* __restrict__ Wu, const float* __restrict__ Wd){
    if (blockIdx.x < 64){
        int c0 = threadIdx.x, c1 = threadIdx.x + 256;
        float s0=0,s1=0,q0=0,q1=0;
        const float* base = x + (size_t)blockIdx.x * 128 * DD;
        for (int r=0;r<128;r++){
            float v0 = base[(size_t)r*DD + c0];
            float v1 = base[(size_t)r*DD + c1];
            s0+=v0; q0+=v0*v0; s1+=v1; q1+=v1*v1;
        }
        float* p = g_part + blockIdx.x*1024;
        p[c0]=s0; p[c1]=s1; p[512+c0]=q0; p[512+c1]=q1;
    } else {
        long e = (long)(blockIdx.x - 64)*1024 + (long)threadIdx.x*4;
        if (e >= TOTW) return;
        const float* src; long base;
        if      (e < OFF_WK)   { src = Wq;   base = OFF_WQ;  }
        else if (e < OFF_WV)   { src = Wk;   base = OFF_WK;  }
        else if (e < OFF_WOG)  { src = Wv;   base = OFF_WV;  }
        else if (e < OFF_WOUT) { src = Wog;  base = OFF_WOG; }
        else if (e < OFF_WG)   { src = Wout; base = OFF_WOUT;}
        else if (e < OFF_WU)   { src = Wg;   base = OFF_WG;  }
        else if (e < OFF_WD)   { src = Wu;   base = OFF_WU;  }
        else                   { src = Wd;   base = OFF_WD;  }
        float4 v = *reinterpret_cast<const float4*>(src + (e - base));
        __half2* d = reinterpret_cast<__half2*>(g_wh + e);
        d[0] = __floats2half2_rn(v.x, v.y);
        d[1] = __floats2half2_rn(v.z, v.w);
    }
}
__global__ void bn_final_kernel(){
    int c = threadIdx.x; // 512
    float s=0,q=0;
    for (int i=0;i<64;i++){ s += g_part[i*1024+c]; q += g_part[i*1024+512+c]; }
    float mu = s * (1.0f/RR);
    float var = q * (1.0f/RR) - mu*mu;
    g_stats[c] = mu;
    g_stats[512+c] = rsqrtf(var + EPS_BN);
}
// bn apply + rmsnorm(norm1_w[0]) fused: writes g_xn, g_h (fp32) and g_yh (fp16)
__global__ void bnapply_rms_kernel(const float* __restrict__ x,
                                   const float* __restrict__ gamma,
                                   const float* __restrict__ beta,
                                   const float* __restrict__ w){
    __shared__ float red[8];
    int r = blockIdx.x, t = threadIdx.x;
    int c0 = t, c1 = t + 256;
    const float* xr = x + (size_t)r*DD;
    float a = (xr[c0]-g_stats[c0])*g_stats[512+c0]*gamma[c0] + beta[c0];
    float b = (xr[c1]-g_stats[c1])*g_stats[512+c1]*gamma[c1] + beta[c1];
    g_xn[(size_t)r*DD+c0] = a; g_xn[(size_t)r*DD+c1] = b;
    g_h [(size_t)r*DD+c0] = a; g_h [(size_t)r*DD+c1] = b;
    float s = a*a + b*b;
    #pragma unroll
    for (int o=16;o;o>>=1) s += __shfl_xor_sync(~0u, s, o);
    if ((t&31)==0) red[t>>5]=s;
    __syncthreads();
    float tot = 0;
    #pragma unroll
    for (int i=0;i<8;i++) tot += red[i];
    float rs = rsqrtf(tot*(1.0f/DD) + EPS_RMS);
    g_yh[(size_t)r*DD+c0] = __float2half(a*rs*w[c0]);
    g_yh[(size_t)r*DD+c1] = __float2half(b*rs*w[c1]);
}

// ---------------- rms norm variants ----------------
__global__ void rmsnorm_h_kernel(const float* __restrict__ x, const float* __restrict__ w,
                                 __half* __restrict__ y){
    __shared__ float red[8];
    int r = blockIdx.x, t = threadIdx.x;
    const float* xr = x + (size_t)r*DD;
    float a = xr[t], b = xr[t+256];
    float s = a*a + b*b;
    #pragma unroll
    for (int o=16;o;o>>=1) s += __shfl_xor_sync(~0u, s, o);
    if ((t&31)==0) red[t>>5]=s;
    __syncthreads();
    float tot = 0;
    #pragma unroll
    for (int i=0;i<8;i++) tot += red[i];
    float rs = rsqrtf(tot*(1.0f/DD) + EPS_RMS);
    __half* yr = y + (size_t)r*DD;
    yr[t]     = __float2half(a*rs*w[t]);
    yr[t+256] = __float2half(b*rs*w[t+256]);
}
__global__ void rmsnorm_f_kernel(const float* __restrict__ x, const float* __restrict__ w,
                                 float* __restrict__ y, long xs){
    __shared__ float red[8];
    int r = blockIdx.x, t = threadIdx.x;
    const float* xr = x + (size_t)r*xs;
    float a = xr[t], b = xr[t+256];
    float s = a*a + b*b;
    #pragma unroll
    for (int o=16;o;o>>=1) s += __shfl_xor_sync(~0u, s, o);
    if ((t&31)==0) red[t>>5]=s;
    __syncthreads();
    float tot = 0;
    #pragma unroll
    for (int i=0;i<8;i++) tot += red[i];
    float rs = rsqrtf(tot*(1.0f/DD) + EPS_RMS);
    float* yr = y + (size_t)r*DD;
    yr[t]     = a*rs*w[t];
    yr[t+256] = b*rs*w[t+256];
}

// ---------------- fp16 tensor-core GEMM ----------------
// C[M,N] = A[M,K] @ B[K,N]; A,B fp16, accum fp32.
// block 128x128, 4 warps of 64x64, K-tile 32, cp.async double buffer, ldmatrix.
// EPI: 0 store fp32, 1 C+=, 2 sigmoid, 3 CH = silu(C)*acc (half out)
#define AP 40          // A row pitch (halves): 32 + 8
#define BP 136         // B row pitch (halves): 128 + 8
#define AS_SZ (128*AP) // 5120
#define BS_SZ (32*BP)  // 4352

template<int EPI>
__global__ __launch_bounds__(128) void hgemm_kernel(
        const __half* __restrict__ A,
        const __half* __restrict__ B0, float* __restrict__ C0,
        const __half* __restrict__ B1, float* __restrict__ C1,
        __half* __restrict__ CH,
        int N, int K){
    __shared__ __half sm[2*(AS_SZ+BS_SZ)];
    __half* As = sm;                 // [2][AS_SZ]
    __half* Bs = sm + 2*AS_SZ;       // [2][BS_SZ]
    const __half* Bm = (blockIdx.z == 0) ? B0 : B1;
    float* C = (blockIdx.z == 0) ? C0 : C1;
    const int tid = threadIdx.x;
    const int lane = tid & 31;
    const int wid = tid >> 5;
    const int g = lane >> 2, t = lane & 3;
    const int mw = (wid >> 1) * 64;
    const int nw = (wid & 1) * 64;
    const __half* Ab = A + (size_t)blockIdx.y * 128 * K;
    const __half* Bb = Bm + (size_t)blockIdx.x * 128;

    // ldmatrix lane address components
    const int lrow = (lane & 7) + ((lane >> 3) & 1) * 8;  // +row within 16
    const int lcol = ((lane >> 3) & 2) * 4;               // +0 or +8 col
    const unsigned smA = (unsigned)__cvta_generic_to_shared(As);
    const unsigned smB = (unsigned)__cvta_generic_to_shared(Bs);

    float acc[4][8][4];
    #pragma unroll
    for (int i=0;i<4;i++)
        #pragma unroll
        for (int j=0;j<8;j++)
            #pragma unroll
            for (int c=0;c<4;c++) acc[i][j][c]=0.f;

    const int KT = K / 32;

    #define LOAD_TILE(kt, buf) do {                                            \
        __half* Ad = As + (buf)*AS_SZ;                                         \
        __half* Bd = Bs + (buf)*BS_SZ;                                         \
        _Pragma("unroll")                                                      \
        for (int ii=0; ii<4; ii++){                                            \
            int idx = tid + ii*128;                                            \
            int m = idx >> 2, c = idx & 3;                                     \
            cp16(Ad + m*AP + c*8, Ab + (size_t)m*K + (kt)*32 + c*8);           \
        }                                                                      \
        _Pragma("unroll")                                                      \
        for (int ii=0; ii<4; ii++){                                            \
            int idx = tid + ii*128;                                            \
            int kr = idx >> 4, c = idx & 15;                                   \
            cp16(Bd + kr*BP + c*8, Bb + (size_t)((kt)*32+kr)*N + c*8);         \
        }                                                                      \
    } while(0)

    LOAD_TILE(0, 0);
    cp_commit();

    for (int kt=0; kt<KT; kt++){
        int buf = kt & 1;
        if (kt+1 < KT){
            LOAD_TILE(kt+1, buf^1);
            cp_commit();
            cp_wait<1>();
        } else {
            cp_wait<0>();
        }
        __syncthreads();
        unsigned baseA = smA + buf*AS_SZ*2;
        unsigned baseB = smB + buf*BS_SZ*2;
        #pragma unroll
        for (int ks=0; ks<2; ks++){
            int k0 = ks*16;
            unsigned af[4][4], bf[4][4];
            #pragma unroll
            for (int i=0;i<4;i++){
                int m0 = mw + i*16;
                unsigned addr = baseA + ((unsigned)(m0 + lrow)*AP + (k0 + lcol))*2;
                ldsm4(af[i][0], af[i][1], af[i][2], af[i][3], addr);
            }
            #pragma unroll
            for (int j2=0;j2<4;j2++){
                int n0 = nw + j2*16;
                unsigned addr = baseB + ((unsigned)(k0 + lrow)*BP + (n0 + lcol))*2;
                ldsm4t(bf[j2][0], bf[j2][1], bf[j2][2], bf[j2][3], addr);
            }
            #pragma unroll
            for (int i=0;i<4;i++){
                #pragma unroll
                for (int j=0;j<8;j++){
                    unsigned b2[2];
                    b2[0] = bf[j>>1][(j&1)*2+0];
                    b2[1] = bf[j>>1][(j&1)*2+1];
                    mma_f16(acc[i][j], af[i], b2);
                }
            }
        }
        __syncthreads();
    }

    // epilogue: c frag (m=g / g+8, n = t*2, t*2+1)
    #pragma unroll
    for (int i=0;i<4;i++){
        #pragma unroll
        for (int j=0;j<8;j++){
            size_t row = (size_t)blockIdx.y*128 + mw + i*16 + g;
            size_t col = (size_t)blockIdx.x*128 + nw + j*8 + t*2;
            #pragma unroll
            for (int h2=0; h2<2; h2++){
                size_t rr = row + h2*8;
                float v0 = acc[i][j][h2*2+0];
                float v1 = acc[i][j][h2*2+1];
                if (EPI==0){
                    float* p = C + rr*N + col;
                    p[0]=v0; p[1]=v1;
                } else if (EPI==1){
                    float* p = C + rr*N + col;
                    p[0]+=v0; p[1]+=v1;
                } else if (EPI==2){
                    float* p = C + rr*N + col;
                    p[0] = 1.0f/(1.0f+expf(-v0));
                    p[1] = 1.0f/(1.0f+expf(-v1));
                } else {
                    const float* p = C + rr*N + col;
                    float g0=p[0], g1v=p[1];
                    __half* q = CH + rr*N + col;
                    q[0] = __float2half(g0*(1.0f/(1.0f+expf(-g0)))*v0);
                    q[1] = __float2half(g1v*(1.0f/(1.0f+expf(-g1v)))*v1);
                }
            }
        }
    }
    #undef LOAD_TILE
}

// ---------------- gate projections (fp16 y input) ----------------
__global__ void gates_kernel(const __half* __restrict__ y,
                             const float* __restrict__ Wi, const float* __restrict__ bi,
                             const float* __restrict__ Wf, const float* __restrict__ bf){
    int warp = (blockIdx.x*blockDim.x + threadIdx.x) >> 5;
    int lane = threadIdx.x & 31;
    if (warp >= RR) return;
    const __half* yr = y + (size_t)warp*DD;
    float si[8]={0,0,0,0,0,0,0,0}, sf[8]={0,0,0,0,0,0,0,0};
    for (int d=lane; d<DD; d+=32){
        float yv = __half2float(yr[d]);
        #pragma unroll
        for (int hh=0; hh<8; hh++){
            si[hh] += yv * Wi[d*HH+hh];
            sf[hh] += yv * Wf[d*HH+hh];
        }
    }
    #pragma unroll
    for (int hh=0; hh<8; hh++){
        #pragma unroll
        for (int o=16;o;o>>=1){
            si[hh]+=__shfl_xor_sync(~0u,si[hh],o);
            sf[hh]+=__shfl_xor_sync(~0u,sf[hh],o);
        }
    }
    if (lane==0){
        int b = warp >> 9, s = warp & 511;
        #pragma unroll
        for (int hh=0;hh<8;hh++){
            g_ig[((b*HH+hh)*SS)+s] = softcapf(si[hh]+bi[hh]);
            g_fg[((b*HH+hh)*SS)+s] = softcapf(sf[hh]+bf[hh]);
        }
    }
}

// ---------------- per-(b,h) prefix scan ----------------
__global__ void scan_kernel(){
    if (threadIdx.x != 0) return;
    int bh = blockIdx.x;
    const float* ig = g_ig + bh*SS;
    const float* fg = g_fg + bh*SS;
    float bc=0.f, cm=-1e30f;
    for (int s=0;s<SS;s++){
        bc += logsigf(fg[s]);
        float c = ig[s] - bc;
        cm = fmaxf(cm, c);
        g_bc[bh*SS+s] = bc;
        g_mv[bh*SS+s] = bc + cm;   // m[t]
    }
}

// ---------------- mLSTM attention (float4 vectorized) ----------------
__global__ __launch_bounds__(64) void attn_kernel(){
    __shared__ float4 Ks[64*8];   // 64 rows x 32 floats
    __shared__ float4 Vs[64*16];  // 64 rows x 64 floats
    __shared__ float bs_s[64], ig_s[64];
    int bh = blockIdx.y; int b = bh >> 3; int h = bh & 7;
    int tt = blockIdx.x;
    int tid = threadIdx.x;
    int t = tt*64 + tid;
    const float4* qp = (const float4*)(g_q + ((size_t)(b*SS)+t)*QKD + h*DQK);
    float4 q4[8];
    #pragma unroll
    for (int d=0;d<8;d++) q4[d] = qp[d];
    float bt = g_bc[bh*SS + t];
    float mt = g_mv[bh*SS + t];
    float4 acc[16];
    #pragma unroll
    for (int j=0;j<16;j++) acc[j] = make_float4(0.f,0.f,0.f,0.f);
    float ssum = 0.f;
    const float scale = 0.17677669529663687f;  // 1/sqrt(32)
    for (int st=0; st<=tt; st++){
        int s0 = st*64;
        #pragma unroll
        for (int ii=0; ii<8; ii++){
            int idx = tid + ii*64;
            int rr = idx >> 3, cc = idx & 7;
            Ks[idx] = *(const float4*)(g_k + ((size_t)(b*SS)+s0+rr)*QKD + h*DQK + cc*4);
        }
        #pragma unroll
        for (int ii=0; ii<16; ii++){
            int idx = tid + ii*64;
            int rr = idx >> 4, cc = idx & 15;
            Vs[idx] = *(const float4*)(g_v + ((size_t)(b*SS)+s0+rr)*VV + h*DV + cc*4);
        }
        bs_s[tid] = g_bc[bh*SS + s0 + tid];
        ig_s[tid] = g_ig[bh*SS + s0 + tid];
        __syncthreads();
        int smax = min(64, t - s0 + 1);
        for (int sl=0; sl<smax; sl++){
            const float4* kp = &Ks[sl*8];
            float dot=0.f;
            #pragma unroll
            for (int d=0;d<8;d++){
                float4 kv = kp[d];
                dot += q4[d].x*kv.x + q4[d].y*kv.y + q4[d].z*kv.z + q4[d].w*kv.w;
            }
            float w = dot * scale * __expf(bt - bs_s[sl] + ig_s[sl] - mt);
            ssum += w;
            const float4* vp = &Vs[sl*16];
            #pragma unroll
            for (int j=0;j<16;j++){
                float4 vv = vp[j];
                acc[j].x += w*vv.x; acc[j].y += w*vv.y;
                acc[j].z += w*vv.z; acc[j].w += w*vv.w;
            }
        }
        __syncthreads();
    }
    float nrm = fmaxf(fabsf(ssum), __expf(-mt));
    float inv = 1.0f/(nrm + EPS_RMS);
    float4* o = (float4*)(g_ht + ((size_t)(b*SS)+t)*VV + h*DV);
    #pragma unroll
    for (int j=0;j<16;j++){
        float4 a = acc[j];
        o[j] = make_float4(a.x*inv, a.y*inv, a.z*inv, a.w*inv);
    }
}

// ---------------- per-head layer norm * mhn_w * og -> fp16 ----------------
__global__ void headnorm_kernel(const float* __restrict__ mhn){
    int r = blockIdx.x;
    int w = threadIdx.x >> 5;      // head
    int lane = threadIdx.x & 31;
    const float* base = g_ht + (size_t)r*VV + w*DV;
    float e0 = base[lane], e1 = base[lane+32];
    float s = e0 + e1;
    #pragma unroll
    for (int o=16;o;o>>=1) s += __shfl_xor_sync(~0u,s,o);
    float mu = s * (1.0f/DV);
    float d0 = e0-mu, d1 = e1-mu;
    float v = d0*d0 + d1*d1;
    #pragma unroll
    for (int o=16;o;o>>=1) v += __shfl_xor_sync(~0u,v,o);
    float rs = rsqrtf(v*(1.0f/DV) + EPS_RMS);
    const float* ogb = g_og + (size_t)r*VV + w*DV;
    __half* dst = g_hth + (size_t)r*VV + w*DV;
    dst[lane]    = __float2half(d0*rs*mhn[w*DV+lane]   * ogb[lane]);
    dst[lane+32] = __float2half(d1*rs*mhn[w*DV+lane+32]* ogb[lane+32]);
}

// ---------------- final heads ----------------
__global__ void bn1_kernel(const float* __restrict__ gamma, const float* __restrict__ beta){
    int c = threadIdx.x; // 512
    float v[16]; float mu=0.f;
    #pragma unroll
    for (int b=0;b<16;b++){ v[b]=g_last[b*DD+c]; mu+=v[b]; }
    mu *= (1.0f/16.0f);
    float var=0.f;
    #pragma unroll
    for (int b=0;b<16;b++){ float d=v[b]-mu; var+=d*d; }
    var *= (1.0f/16.0f);
    float rs = rsqrtf(var + EPS_BN);
    #pragma unroll
    for (int b=0;b<16;b++) g_last[b*DD+c] = (v[b]-mu)*rs*gamma[c] + beta[c];
}
__global__ void fc1_kernel(const float* __restrict__ W, const float* __restrict__ bias){
    __shared__ float xr[512];
    int b = blockIdx.x; int j = threadIdx.x; // 256
    xr[j]     = g_last[b*DD + j];
    xr[j+256] = g_last[b*DD + j + 256];
    __syncthreads();
    float s=0.f;
    #pragma unroll 8
    for (int k=0;k<512;k++) s += xr[k]*W[k*256+j];
    g_o1[b*256+j] = s + bias[j];
}
__global__ void bn2gelu_kernel(const float* __restrict__ gamma, const float* __restrict__ beta){
    int j = threadIdx.x; // 256
    float v[16]; float mu=0.f;
    #pragma unroll
    for (int b=0;b<16;b++){ v[b]=g_o1[b*256+j]; mu+=v[b]; }
    mu *= (1.0f/16.0f);
    float var=0.f;
    #pragma unroll
    for (int b=0;b<16;b++){ float d=v[b]-mu; var+=d*d; }
    var *= (1.0f/16.0f);
    float rs = rsqrtf(var + EPS_BN);
    #pragma unroll
    for (int b=0;b<16;b++){
        float t = (v[b]-mu)*rs*gamma[j] + beta[j];
        g_o1[b*256+j] = 0.5f*t*(1.0f + erff(t*0.7071067811865475f));
    }
}
__global__ void fc2_kernel(const float* __restrict__ W, const float* __restrict__ bias){
    __shared__ float red[256];
    int b = blockIdx.x; int j = threadIdx.x;
    red[j] = g_o1[b*256+j]*W[j];
    __syncthreads();
    for (int o=128;o;o>>=1){ if(j<o) red[j]+=red[j+o]; __syncthreads(); }
    if (j==0) g_o2[b] = red[0] + bias[0];
}
__global__ void res_out_kernel(const float* __restrict__ resW, const float* __restrict__ resb,
                               float* __restrict__ out){
    int warp = (blockIdx.x*blockDim.x + threadIdx.x) >> 5;
    int lane = threadIdx.x & 31;
    if (warp >= RR) return;
    const float* xr = g_xn + (size_t)warp*DD;
    float s=0.f;
    for (int d=lane; d<DD; d+=32) s += xr[d]*resW[d];
    #pragma unroll
    for (int o=16;o;o>>=1) s += __shfl_xor_sync(~0u,s,o);
    if (lane==0){
        float v = s + resb[0] + g_o2[warp>>9];
        out[warp] = fmaxf(v, 0.f);
    }
}

// ---------------- host driver ----------------
extern "C" void kernel_launch(void* const* d_in, const int* in_sizes, int n_in,
                              void* d_out, int out_size){
    const float* x        = (const float*)d_in[0];
    const float* bng      = (const float*)d_in[1];
    const float* bnb      = (const float*)d_in[2];
    const float* norm1_w  = (const float*)d_in[3];
    const float* norm2_w  = (const float*)d_in[4];
    const float* Wq       = (const float*)d_in[5];
    const float* Wk       = (const float*)d_in[6];
    const float* Wv       = (const float*)d_in[7];
    const float* Wog      = (const float*)d_in[8];
    const float* Wi       = (const float*)d_in[9];
    const float* bi       = (const float*)d_in[10];
    const float* Wf       = (const float*)d_in[11];
    const float* bf       = (const float*)d_in[12];
    const float* mhn_w    = (const float*)d_in[13];
    const float* Wout     = (const float*)d_in[14];
    const float* Wg       = (const float*)d_in[15];
    const float* Wu       = (const float*)d_in[16];
    const float* Wd       = (const float*)d_in[17];
    const float* fnorm_w  = (const float*)d_in[18];
    const float* bn1_g    = (const float*)d_in[19];
    const float* bn1_b    = (const float*)d_in[20];
    const float* fc1_W    = (const float*)d_in[21];
    const float* fc1_b    = (const float*)d_in[22];
    const float* bn2_g    = (const float*)d_in[23];
    const float* bn2_b    = (const float*)d_in[24];
    const float* fc2_W    = (const float*)d_in[25];
    const float* fc2_b    = (const float*)d_in[26];
    const float* res_W    = (const float*)d_in[27];
    const float* res_b    = (const float*)d_in[28];
    float* out = (float*)d_out;

    float *p_q,*p_k,*p_v,*p_og,*p_ht,*p_h,*p_g1,*p_last;
    __half *p_wh,*p_yh,*p_hth,*p_g1h;
    cudaGetSymbolAddress((void**)&p_q,  g_q);
    cudaGetSymbolAddress((void**)&p_k,  g_k);
    cudaGetSymbolAddress((void**)&p_v,  g_v);
    cudaGetSymbolAddress((void**)&p_og, g_og);
    cudaGetSymbolAddress((void**)&p_ht, g_ht);
    cudaGetSymbolAddress((void**)&p_h,  g_h);
    cudaGetSymbolAddress((void**)&p_g1, g_gu1);
    cudaGetSymbolAddress((void**)&p_last, g_last);
    cudaGetSymbolAddress((void**)&p_wh,  g_wh);
    cudaGetSymbolAddress((void**)&p_yh,  g_yh);
    cudaGetSymbolAddress((void**)&p_hth, g_hth);
    cudaGetSymbolAddress((void**)&p_g1h, g_g1h);

    // 1: bn partial + weight conversion (fused)
    bnpart_conv_kernel<<<64 + (int)((TOTW + 1023)/1024), 256>>>(x, Wq, Wk, Wv, Wog, Wout, Wg, Wu, Wd);
    // 2: bn stats
    bn_final_kernel<<<1,512>>>();
    // 3: bn apply + first rmsnorm (fused)
    bnapply_rms_kernel<<<RR,256>>>(x, bng, bnb, norm1_w);

    for (int l=0;l<LL;l++){
        const __half* Wq_h  = p_wh + OFF_WQ  + (size_t)l*DD*QKD;
        const __half* Wk_h  = p_wh + OFF_WK  + (size_t)l*DD*QKD;
        const __half* Wv_h  = p_wh + OFF_WV  + (size_t)l*DD*VV;
        const __half* Wog_h = p_wh + OFF_WOG + (size_t)l*DD*VV;
        const __half* Wout_h= p_wh + OFF_WOUT+ (size_t)l*VV*DD;
        const __half* Wg_h  = p_wh + OFF_WG  + (size_t)l*DD*FF;
        const __half* Wu_h  = p_wh + OFF_WU  + (size_t)l*DD*FF;
        const __half* Wd_h  = p_wh + OFF_WD  + (size_t)l*FF*DD;
        const float* Wi_l = Wi + (size_t)l*DD*HH;
        const float* Wf_l = Wf + (size_t)l*DD*HH;

        if (l > 0)
            rmsnorm_h_kernel<<<RR,256>>>(p_h, norm1_w + l*DD, p_yh);

        // 4 (l=0): q & k dual launch — this is the ncu-profiled kernel
        hgemm_kernel<0><<<dim3(QKD/128, RR/128, 2),128>>>(p_yh, Wq_h, p_q, Wk_h, p_k, nullptr, QKD, DD);
        hgemm_kernel<0><<<dim3(VV/128,  RR/128, 1),128>>>(p_yh, Wv_h, p_v, Wv_h, p_v, nullptr, VV, DD);
        hgemm_kernel<2><<<dim3(VV/128,  RR/128, 1),128>>>(p_yh, Wog_h,p_og,Wog_h,p_og,nullptr, VV, DD);
        gates_kernel<<<RR/8,256>>>(p_yh, Wi_l, bi + l*HH, Wf_l, bf + l*HH);
        scan_kernel<<<BB*HH,32>>>();

        attn_kernel<<<dim3(SS/64, BB*HH),64>>>();

        headnorm_kernel<<<RR,256>>>(mhn_w + l*VV);
        hgemm_kernel<1><<<dim3(DD/128, RR/128, 1),128>>>(p_hth, Wout_h, p_h, Wout_h, p_h, nullptr, DD, VV);

        rmsnorm_h_kernel<<<RR,256>>>(p_h, norm2_w + l*DD, p_yh);
        hgemm_kernel<0><<<dim3(FF/128, RR/128, 1),128>>>(p_yh, Wg_h, p_g1, Wg_h, p_g1, nullptr, FF, DD);
        hgemm_kernel<3><<<dim3(FF/128, RR/128, 1),128>>>(p_yh, Wu_h, p_g1, Wu_h, p_g1, p_g1h, FF, DD);
        hgemm_kernel<1><<<dim3(DD/128, RR/128, 1),128>>>(p_g1h, Wd_h, p_h, Wd_h, p_h, nullptr, DD, FF);
    }

    // final rms norm on last row of each batch -> g_last [16,512]
    rmsnorm_f_kernel<<<BB,256>>>(p_h + (size_t)(SS-1)*DD, fnorm_w, p_last, (long)SS*DD);

    bn1_kernel<<<1,512>>>(bn1_g, bn1_b);
    fc1_kernel<<<BB,256>>>(fc1_W, fc1_b);
    bn2gelu_kernel<<<1,256>>>(bn2_g, bn2_b);
    fc2_kernel<<<BB,256>>>(fc2_W, fc2_b);
    res_out_kernel<<<RR/8,256>>>(res_W, res_b, out);
    (void)in_sizes; (void)n_in; (void)out_size;
}